// round 14
// baseline (speedup 1.0000x reference)
#include <cuda_runtime.h>
#include <cuda_bf16.h>
#include <math.h>

// ---------------- problem constants ----------------
#define BB  4
#define CC  64
#define HH  64
#define WW  64
#define HW  4096      // 64*64
#define KCH 192       // C*Q
#define PP  64
#define NTILE 1024    // 32x32 sp tiles per batch

typedef unsigned long long u64;

// ---------------- scratch (no allocations allowed) ----------------
__device__ __align__(128) float g_top[BB * PP * HW];        // (b,p,n)
__device__ __align__(128) float g_centerT[BB * HW * PP];    // (b,n,p)
__device__ __align__(128) float g_bottomT[BB * HW * CC];    // (b,m,c)
// exp(sp - tile_max) as ONE bf16 plane, packed 2 cols per u32 (denominator uses
// the SAME rounded values, so dominant-term rounding cancels in the softmax).
__device__ __align__(128) unsigned g_sph[(size_t)BB * HW * HW / 2];  // 134MB
__device__ __align__(128) float g_spv[2][BB * HW * CC];     // split-K partials
__device__ __align__(128) float g_tmax[BB][NTILE];
__device__ __align__(128) float g_tsum[BB][NTILE];
__device__ float g_max[BB];
__device__ float g_sum[BB];

// ---------------- packed f32x2 helpers ----------------
__device__ __forceinline__ u64 pk2(float lo, float hi) {
    u64 r; asm("mov.b64 %0,{%1,%2};" : "=l"(r) : "f"(lo), "f"(hi)); return r;
}
__device__ __forceinline__ u64 dup2(float a) { return pk2(a, a); }
__device__ __forceinline__ void up2(u64 v, float& lo, float& hi) {
    asm("mov.b64 {%0,%1},%2;" : "=f"(lo), "=f"(hi) : "l"(v));
}
__device__ __forceinline__ u64 fma2(u64 a, u64 b, u64 c) {
    u64 d; asm("fma.rn.f32x2 %0,%1,%2,%3;" : "=l"(d) : "l"(a), "l"(b), "l"(c)); return d;
}
__device__ __forceinline__ u64 mul2(u64 a, u64 b) {
    u64 d; asm("mul.rn.f32x2 %0,%1,%2;" : "=l"(d) : "l"(a), "l"(b)); return d;
}
__device__ __forceinline__ u64 add2(u64 a, u64 b) {
    u64 d; asm("add.rn.f32x2 %0,%1,%2;" : "=l"(d) : "l"(a), "l"(b)); return d;
}

// FMA-pipe exp (scalar), x <= 0 expected, clamped at -80.
__device__ __forceinline__ float fexp(float x) {
    x = fmaxf(x, -80.0f);
    float t = x * 1.4426950408889634f;
    float n = rintf(t);
    float f = t - n;
    float p = 1.5403530e-4f;
    p = fmaf(p, f, 1.3333558e-3f);
    p = fmaf(p, f, 9.6181291e-3f);
    p = fmaf(p, f, 5.5504109e-2f);
    p = fmaf(p, f, 2.4022651e-1f);
    p = fmaf(p, f, 6.9314718e-1f);
    p = fmaf(p, f, 1.0f);
    int e = (int)n;
    return p * __int_as_float((e + 127) << 23);
}

// packed exp2-based exp(x - off): caller folds offset into TOFF
__device__ __forceinline__ u64 fexp2pair(u64 x2, u64 L2E, u64 TOFF,
                                         u64 MAGIC, u64 NMAG, u64 NEG1,
                                         u64 C6, u64 C5, u64 C4, u64 C3,
                                         u64 C2, u64 C1, u64 ONE) {
    u64 t  = fma2(x2, L2E, TOFF);
    u64 z  = add2(t, MAGIC);
    u64 nf = add2(z, NMAG);
    u64 f  = fma2(nf, NEG1, t);
    u64 p  = fma2(C6, f, C5);
    p = fma2(p, f, C4); p = fma2(p, f, C3);
    p = fma2(p, f, C2); p = fma2(p, f, C1);
    p = fma2(p, f, ONE);
    unsigned zl, zh;
    asm("mov.b64 {%0,%1},%2;" : "=r"(zl), "=r"(zh) : "l"(z));
    int el = max((int)zl - 0x4B400000, -126) + 127;
    int eh = max((int)zh - 0x4B400000, -126) + 127;
    u64 s = pk2(__int_as_float(el << 23), __int_as_float(eh << 23));
    return mul2(p, s);
}

// ---------------- mma.sync / ldmatrix helpers (baseline PTX) ----------------
__device__ __forceinline__ void ldsm_x4(unsigned* r, unsigned a) {
    asm volatile("ldmatrix.sync.aligned.m8n8.x4.shared.b16 {%0,%1,%2,%3}, [%4];"
        : "=r"(r[0]), "=r"(r[1]), "=r"(r[2]), "=r"(r[3]) : "r"(a));
}
__device__ __forceinline__ void ldsm_x2t(unsigned* r, unsigned a) {
    asm volatile("ldmatrix.sync.aligned.m8n8.x2.trans.shared.b16 {%0,%1}, [%2];"
        : "=r"(r[0]), "=r"(r[1]) : "r"(a));
}
__device__ __forceinline__ void mma_bf16(float* d, const unsigned* a, const unsigned* b) {
    asm volatile("mma.sync.aligned.m16n8k16.row.col.f32.bf16.bf16.f32 "
        "{%0,%1,%2,%3}, {%4,%5,%6,%7}, {%8,%9}, {%0,%1,%2,%3};"
        : "+f"(d[0]), "+f"(d[1]), "+f"(d[2]), "+f"(d[3])
        : "r"(a[0]), "r"(a[1]), "r"(a[2]), "r"(a[3]), "r"(b[0]), "r"(b[1]));
}

// split one float4 into hi/lo bf16x2 pairs
__device__ __forceinline__ void cvt4(float4 v, unsigned* hi, unsigned* lo) {
    float a[4] = {v.x, v.y, v.z, v.w};
    #pragma unroll
    for (int p = 0; p < 2; p++) {
        __nv_bfloat162 h = __floats2bfloat162_rn(a[2*p], a[2*p+1]);
        float2 f = __bfloat1622float2(h);
        __nv_bfloat162 l = __floats2bfloat162_rn(a[2*p] - f.x, a[2*p+1] - f.y);
        hi[p] = *(unsigned*)&h;
        lo[p] = *(unsigned*)&l;
    }
}

// ---------------- K2: 1x1 SelfONN convs (top & center), powers inline, FFMA2 --------
__global__ void k_proj(const float* __restrict__ x,
                       const float* __restrict__ top_w, const float* __restrict__ top_b,
                       const float* __restrict__ cen_w, const float* __restrict__ cen_b) {
    __shared__ __align__(16) float As_t[32 * 68];
    __shared__ __align__(16) float As_c[32 * 68];
    __shared__ __align__(16) float Bs[32 * 64];
    int b  = blockIdx.y;
    int n0 = blockIdx.x * 64;
    int tid = threadIdx.x;
    int p0 = (tid >> 4) * 4;
    int j0 = (tid & 15) * 4;
    u64 at[4][2], ac[4][2];
    #pragma unroll
    for (int u = 0; u < 4; u++) { at[u][0] = at[u][1] = 0ull; ac[u][0] = ac[u][1] = 0ull; }

    for (int kc = 0; kc < KCH; kc += 32) {
        int q = kc >> 6;
        #pragma unroll
        for (int it = 0; it < 2; it++) {
            int f4 = tid + it * 256;
            int p = f4 >> 3, k4 = f4 & 7;
            float4 vt = *(const float4*)(top_w + p * KCH + kc + 4 * k4);
            float4 vc = *(const float4*)(cen_w + p * KCH + kc + 4 * k4);
            As_t[(4*k4+0)*68 + p] = vt.x; As_t[(4*k4+1)*68 + p] = vt.y;
            As_t[(4*k4+2)*68 + p] = vt.z; As_t[(4*k4+3)*68 + p] = vt.w;
            As_c[(4*k4+0)*68 + p] = vc.x; As_c[(4*k4+1)*68 + p] = vc.y;
            As_c[(4*k4+2)*68 + p] = vc.z; As_c[(4*k4+3)*68 + p] = vc.w;
        }
        #pragma unroll
        for (int it = 0; it < 2; it++) {
            int f4 = tid + it * 256;
            int k = f4 >> 4, j4 = f4 & 15;
            int c = (kc + k) & 63;
            float4 v = *(const float4*)(x + ((b * CC + c) << 12) + n0 + 4 * j4);
            if (q >= 1) { v.x *= v.x ; v.y *= v.y ; v.z *= v.z ; v.w *= v.w; }
            if (q == 2) {
                float4 v1 = *(const float4*)(x + ((b * CC + c) << 12) + n0 + 4 * j4);
                v.x *= v1.x; v.y *= v1.y; v.z *= v1.z; v.w *= v1.w;
            }
            *(float4*)(Bs + k * 64 + 4 * j4) = v;
        }
        __syncthreads();
        #pragma unroll 8
        for (int k = 0; k < 32; k++) {
            float a1[4]; *(float4*)a1 = *(float4*)(As_t + k * 68 + p0);
            float a2[4]; *(float4*)a2 = *(float4*)(As_c + k * 68 + p0);
            ulonglong2 bq = *(const ulonglong2*)(Bs + k * 64 + j0);
            u64 b2[2] = {bq.x, bq.y};
            #pragma unroll
            for (int u = 0; u < 4; u++) {
                u64 d1 = dup2(a1[u]);
                u64 d2 = dup2(a2[u]);
                at[u][0] = fma2(d1, b2[0], at[u][0]);
                at[u][1] = fma2(d1, b2[1], at[u][1]);
                ac[u][0] = fma2(d2, b2[0], ac[u][0]);
                ac[u][1] = fma2(d2, b2[1], ac[u][1]);
            }
        }
        __syncthreads();
    }
    #pragma unroll
    for (int u = 0; u < 4; u++) {
        float bt = top_b[p0 + u], bc = cen_b[p0 + u];
        float4 o, oc4;
        up2(at[u][0], o.x, o.y); up2(at[u][1], o.z, o.w);
        up2(ac[u][0], oc4.x, oc4.y); up2(ac[u][1], oc4.z, oc4.w);
        o.x += bt; o.y += bt; o.z += bt; o.w += bt;
        *(float4*)(g_top + b * (PP * HW) + (p0 + u) * HW + n0 + j0) = o;
        g_centerT[b * (HW * PP) + (n0 + j0 + 0) * PP + p0 + u] = oc4.x + bc;
        g_centerT[b * (HW * PP) + (n0 + j0 + 1) * PP + p0 + u] = oc4.y + bc;
        g_centerT[b * (HW * PP) + (n0 + j0 + 2) * PP + p0 + u] = oc4.z + bc;
        g_centerT[b * (HW * PP) + (n0 + j0 + 3) * PP + p0 + u] = oc4.w + bc;
    }
}

// ---------------- K3/K7: 3x3 SelfONN conv, chunked implicit GEMM, FFMA2 ----------------
template <bool FINAL>
__global__ void __launch_bounds__(512, 2)
k_conv3(const float* __restrict__ w, const float* __restrict__ bias,
        const float* __restrict__ x, float* __restrict__ out) {
    __shared__ __align__(16) float s_in[8 * 4 * 68];
    __shared__ __align__(16) float s_w[72 * 68];
    int b   = blockIdx.y;
    int h0  = blockIdx.x * 2;
    int tid = threadIdx.x;
    int g    = tid & 31;
    int r    = g >> 4;
    int col0 = (g & 15) * 4;
    int oc0  = (tid >> 5) * 4;
    u64 acc[2][4];
    #pragma unroll
    for (int p = 0; p < 2; p++)
        #pragma unroll
        for (int v = 0; v < 4; v++) acc[p][v] = 0ull;

    for (int kc = 0; kc < KCH; kc += 8) {
        int qi    = kc >> 6;
        int cbase = kc & 63;
        #pragma unroll
        for (int it = 0; it < 5; it++) {
            int idx = tid + it * 512;
            if (idx < 8 * 4 * 68) {
                int c   = idx / 272;
                int rem = idx - c * 272;
                int rr  = rem / 68;
                int ic  = rem - rr * 68;
                int gh = h0 - 1 + rr;
                int gw = ic - 1;
                float v = 0.0f;
                if ((unsigned)gh < HH && (unsigned)gw < WW) {
                    int gidx = ((b * CC + cbase + c) << 12) + (gh << 6) + gw;
                    float y = x[gidx];
                    if (FINAL) y += g_spv[0][gidx] + g_spv[1][gidx];
                    v = y;
                    if (qi >= 1) v *= y;
                    if (qi == 2) v *= y;
                }
                s_in[idx] = v;
            }
        }
        #pragma unroll
        for (int it = 0; it < 9; it++) {
            int i = tid + it * 512;
            int oc  = i / 72;
            int rem = i - oc * 72;
            s_w[rem * 68 + oc] = w[(oc * KCH + kc) * 9 + rem];
        }
        __syncthreads();
        #pragma unroll
        for (int c = 0; c < 8; c++) {
            #pragma unroll
            for (int dy = 0; dy < 3; dy++) {
                const float* rowp = s_in + c * 272 + (r + dy) * 68 + col0;
                float4 t0 = *(const float4*)rowp;
                float2 t1 = *(const float2*)(rowp + 4);
                u64 wd[6];
                wd[0] = dup2(t0.x); wd[1] = dup2(t0.y); wd[2] = dup2(t0.z);
                wd[3] = dup2(t0.w); wd[4] = dup2(t1.x); wd[5] = dup2(t1.y);
                #pragma unroll
                for (int dx = 0; dx < 3; dx++) {
                    ulonglong2 wp = *(const ulonglong2*)
                        (s_w + ((c * 3 + dy) * 3 + dx) * 68 + oc0);
                    #pragma unroll
                    for (int v = 0; v < 4; v++) {
                        acc[0][v] = fma2(wp.x, wd[dx + v], acc[0][v]);
                        acc[1][v] = fma2(wp.y, wd[dx + v], acc[1][v]);
                    }
                }
            }
        }
        __syncthreads();
    }

    float av[4][4];
    #pragma unroll
    for (int p = 0; p < 2; p++)
        #pragma unroll
        for (int v = 0; v < 4; v++)
            up2(acc[p][v], av[2*p][v], av[2*p+1][v]);
    float bs[4];
    #pragma unroll
    for (int u = 0; u < 4; u++) bs[u] = bias[oc0 + u];
    int px_row = (h0 + r) << 6;
    if (FINAL) {
        #pragma unroll
        for (int u = 0; u < 4; u++) {
            float4 o;
            o.x = av[u][0] + bs[u]; o.y = av[u][1] + bs[u];
            o.z = av[u][2] + bs[u]; o.w = av[u][3] + bs[u];
            *(float4*)(out + ((b * CC + oc0 + u) << 12) + px_row + col0) = o;
        }
    } else {
        #pragma unroll
        for (int v = 0; v < 4; v++) {
            float4 o;
            o.x = av[0][v] + bs[0]; o.y = av[1][v] + bs[1];
            o.z = av[2][v] + bs[2]; o.w = av[3][v] + bs[3];
            *(float4*)(g_bottomT + b * (HW * CC) + (px_row + col0 + v) * CC + oc0) = o;
        }
    }
}

// ---------------- K4: QK via mma.sync bf16-split + tile-local softmax ----------------
// Epilogue stores exp(sp - tmax) as ONE bf16 plane; tile sums use the ROUNDED values.
#define OFF_A_HI  128                       // [128 n][72 k] bf16 (144B rows)
#define OFF_A_LO  (OFF_A_HI + 128*144)
#define OFF_B_HI  (OFF_A_LO + 128*144)      // [64 k][136 m] bf16 (272B rows)
#define OFF_B_LO  (OFF_B_HI + 64*272)
#define SMEM_QK   (OFF_B_LO + 64*272)       // 71808 B

__global__ void __launch_bounds__(256, 2)
k_qk_mma() {
    extern __shared__ char smem[];
    unsigned sb;
    asm("{ .reg .u64 t; cvta.to.shared.u64 t, %1; cvt.u32.u64 %0, t; }"
        : "=r"(sb) : "l"(smem));
    int b  = blockIdx.z;
    int m0 = blockIdx.x * 128;
    int n0 = blockIdx.y * 128;
    int tid = threadIdx.x;
    int wid = tid >> 5, lid = tid & 31;
    float* s_red = (float*)smem;

    // ---- stage A (centerT rows, hi/lo) ----
    const float* Ag = g_centerT + (size_t)b * (HW * PP);
    #pragma unroll 2
    for (int it = 0; it < 8; it++) {
        int idx = tid + it * 256;          // 2048: n(128) x kf4(16)
        int n = idx >> 4, kf4 = idx & 15;
        float4 v = *(const float4*)(Ag + (n0 + n) * PP + 4 * kf4);
        unsigned hi[2], lo[2];
        cvt4(v, hi, lo);
        *(uint2*)(smem + OFF_A_HI + n * 144 + 8 * kf4) = make_uint2(hi[0], hi[1]);
        *(uint2*)(smem + OFF_A_LO + n * 144 + 8 * kf4) = make_uint2(lo[0], lo[1]);
    }
    // ---- stage B (top rows [k][m], hi/lo) ----
    const float* Bg = g_top + (size_t)b * (PP * HW) + m0;
    #pragma unroll 2
    for (int it = 0; it < 8; it++) {
        int idx = tid + it * 256;          // 2048: k(64) x mf4(32)
        int k = idx >> 5, mf4 = idx & 31;
        float4 v = *(const float4*)(Bg + k * HW + 4 * mf4);
        unsigned hi[2], lo[2];
        cvt4(v, hi, lo);
        *(uint2*)(smem + OFF_B_HI + k * 272 + 8 * mf4) = make_uint2(hi[0], hi[1]);
        *(uint2*)(smem + OFF_B_LO + k * 272 + 8 * mf4) = make_uint2(lo[0], lo[1]);
    }
    __syncthreads();

    // ---- warp tiling: warp_n = wid>>1 (4 x 32 rows), warp_m = wid&1 (2 x 64 cols) ----
    int wn = (wid >> 1) * 32;
    int wm = (wid & 1) * 64;
    float acc[2][8][4];
    #pragma unroll
    for (int mt = 0; mt < 2; mt++)
        #pragma unroll
        for (int nt = 0; nt < 8; nt++)
            #pragma unroll
            for (int e = 0; e < 4; e++) acc[mt][nt][e] = 0.0f;

    int arow = wn + (lid & 15);
    int acolB = (lid >> 4) * 8;
    int bkrow = (lid & 15);

    #pragma unroll
    for (int ks = 0; ks < 4; ks++) {
        int k0 = ks * 16;
        unsigned ah[2][4], al[2][4];
        #pragma unroll
        for (int mt = 0; mt < 2; mt++) {
            unsigned aaddr = sb + OFF_A_HI + (arow + mt * 16) * 144 + (k0 + acolB) * 2;
            ldsm_x4(ah[mt], aaddr);
            ldsm_x4(al[mt], aaddr + (OFF_A_LO - OFF_A_HI));
        }
        unsigned bf[8][2];
        #pragma unroll
        for (int nt = 0; nt < 8; nt++)
            ldsm_x2t(bf[nt], sb + OFF_B_HI + (k0 + bkrow) * 272 + (wm + nt * 8) * 2);
        #pragma unroll
        for (int mt = 0; mt < 2; mt++)
            #pragma unroll
            for (int nt = 0; nt < 8; nt++) {
                mma_bf16(acc[mt][nt], ah[mt], bf[nt]);
                mma_bf16(acc[mt][nt], al[mt], bf[nt]);
            }
        #pragma unroll
        for (int nt = 0; nt < 8; nt++)
            ldsm_x2t(bf[nt], sb + OFF_B_LO + (k0 + bkrow) * 272 + (wm + nt * 8) * 2);
        #pragma unroll
        for (int mt = 0; mt < 2; mt++)
            #pragma unroll
            for (int nt = 0; nt < 8; nt++)
                mma_bf16(acc[mt][nt], ah[mt], bf[nt]);
    }

    // ---- tile max (block-wide) ----
    float mx = -INFINITY;
    #pragma unroll
    for (int mt = 0; mt < 2; mt++)
        #pragma unroll
        for (int nt = 0; nt < 8; nt++)
            #pragma unroll
            for (int e = 0; e < 4; e++)
                mx = fmaxf(mx, acc[mt][nt][e]);
    #pragma unroll
    for (int off = 16; off > 0; off >>= 1)
        mx = fmaxf(mx, __shfl_xor_sync(0xffffffffu, mx, off));
    if (lid == 0) s_red[wid] = mx;
    __syncthreads();
    float tmax = s_red[0];
    #pragma unroll
    for (int i = 1; i < 8; i++) tmax = fmaxf(tmax, s_red[i]);

    // ---- packed exp(sp - tmax) -> bf16, sum the ROUNDED values, store ----
    const u64 L2E   = dup2(1.4426950408889634f);
    const u64 TOFF  = dup2(-tmax * 1.4426950408889634f);
    const u64 MAGIC = dup2(12582912.0f);
    const u64 NMAG  = dup2(-12582912.0f);
    const u64 NEG1  = dup2(-1.0f);
    const u64 C6 = dup2(1.5403530e-4f), C5 = dup2(1.3333558e-3f);
    const u64 C4 = dup2(9.6181291e-3f), C3 = dup2(5.5504109e-2f);
    const u64 C2 = dup2(2.4022651e-1f), C1 = dup2(6.9314718e-1f);
    const u64 ONE = dup2(1.0f);
    float ssum = 0.0f;
    unsigned* Ho = g_sph + ((size_t)b << 23);
    int rbase = n0 + wn + (lid >> 2);
    int cbase = m0 + wm + (lid & 3) * 2;
    #pragma unroll
    for (int mt = 0; mt < 2; mt++)
        #pragma unroll
        for (int nt = 0; nt < 8; nt++) {
            u64 e01 = fexp2pair(pk2(acc[mt][nt][0], acc[mt][nt][1]),
                                L2E, TOFF, MAGIC, NMAG, NEG1,
                                C6, C5, C4, C3, C2, C1, ONE);
            u64 e23 = fexp2pair(pk2(acc[mt][nt][2], acc[mt][nt][3]),
                                L2E, TOFF, MAGIC, NMAG, NEG1,
                                C6, C5, C4, C3, C2, C1, ONE);
            float e0, e1, e2, e3;
            up2(e01, e0, e1); up2(e23, e2, e3);
            __nv_bfloat162 h01 = __floats2bfloat162_rn(e0, e1);
            __nv_bfloat162 h23 = __floats2bfloat162_rn(e2, e3);
            float2 f0 = __bfloat1622float2(h01);
            float2 f1 = __bfloat1622float2(h23);
            ssum += (f0.x + f0.y) + (f1.x + f1.y);
            int cc = cbase + nt * 8;
            Ho[((size_t)(rbase + mt * 16) * HW + cc) >> 1] = *(unsigned*)&h01;
            Ho[((size_t)(rbase + mt * 16 + 8) * HW + cc) >> 1] = *(unsigned*)&h23;
        }
    #pragma unroll
    for (int off = 16; off > 0; off >>= 1)
        ssum += __shfl_xor_sync(0xffffffffu, ssum, off);
    __syncthreads();
    if (lid == 0) s_red[wid] = ssum;
    __syncthreads();
    if (tid == 0) {
        float t = 0.0f;
        #pragma unroll
        for (int i = 0; i < 8; i++) t += s_red[i];
        int tile = blockIdx.y * 32 + blockIdx.x;
        g_tmax[b][tile] = tmax;
        g_tsum[b][tile] = t;
    }
}

// ---------------- K5: combine per-tile (max,sum) -> global (max,sum) ----------------
__global__ void k_combine() {
    int b = blockIdx.x;
    int tid = threadIdx.x;               // 1024 threads, one per tile
    __shared__ float s_red[32];
    float v = g_tmax[b][tid];
    float mx = v;
    #pragma unroll
    for (int off = 16; off > 0; off >>= 1)
        mx = fmaxf(mx, __shfl_xor_sync(0xffffffffu, mx, off));
    if ((tid & 31) == 0) s_red[tid >> 5] = mx;
    __syncthreads();
    if (tid < 32) {
        float m2 = s_red[tid];
        #pragma unroll
        for (int off = 16; off > 0; off >>= 1)
            m2 = fmaxf(m2, __shfl_xor_sync(0xffffffffu, m2, off));
        if (tid == 0) s_red[0] = m2;
    }
    __syncthreads();
    float gmax = s_red[0];
    __syncthreads();
    float part = g_tsum[b][tid] * fexp(v - gmax);
    #pragma unroll
    for (int off = 16; off > 0; off >>= 1)
        part += __shfl_xor_sync(0xffffffffu, part, off);
    __shared__ float s_sum[32];
    if ((tid & 31) == 0) s_sum[tid >> 5] = part;
    __syncthreads();
    if (tid < 32) {
        float t = s_sum[tid];
        #pragma unroll
        for (int off = 16; off > 0; off >>= 1)
            t += __shfl_xor_sync(0xffffffffu, t, off);
        if (tid == 0) { g_max[b] = gmax; g_sum[b] = t; }
    }
}

// ---------------- K6: spv = E @ bottomT via mma.sync (E bf16, B split), split-K 2 ----
#define AV_A_HI 0                           // [128 n][72 k] bf16 (144B rows)
#define AV_B_HI (AV_A_HI + 128*144)         // [64 k][72 c] bf16 (144B rows)
#define AV_B_LO (AV_B_HI + 64*144)
#define SMEM_AV (AV_B_LO + 64*144)          // 36864 B

__global__ void __launch_bounds__(256, 3)
k_av_mma() {
    extern __shared__ char smem[];
    unsigned sb;
    asm("{ .reg .u64 t; cvta.to.shared.u64 t, %1; cvt.u32.u64 %0, t; }"
        : "=r"(sb) : "l"(smem));
    int b  = blockIdx.z;
    int ks = blockIdx.y;
    int n0 = blockIdx.x * 128;
    int tid = threadIdx.x;
    int wid = tid >> 5, lid = tid & 31;
    int wn = (wid >> 1) * 32;       // warp rows
    int wc = (wid & 1) * 32;        // warp cols
    const unsigned* Hp = g_sph + ((size_t)b << 23);
    const float* BT = g_bottomT + b * (HW * CC);
    float gmax = g_max[b];
    int trow = (n0 >> 7) * 32;

    float acc[2][4][4];
    #pragma unroll
    for (int mt = 0; mt < 2; mt++)
        #pragma unroll
        for (int nt = 0; nt < 4; nt++)
            #pragma unroll
            for (int e = 0; e < 4; e++) acc[mt][nt][e] = 0.0f;

    int arow = wn + (lid & 15);
    int acolB = (lid >> 4) * 8;
    int bkrow = (lid & 15);

    for (int kc = 0; kc < 2048; kc += 64) {
        int kbase = ks * 2048 + kc;
        // ---- stage A: bf16 E plane straight from gmem ----
        #pragma unroll
        for (int it = 0; it < 4; it++) {
            int idx = tid + it * 256;              // 1024: row(128) x j(8)
            int row = idx >> 3, j = idx & 7;
            size_t off = (size_t)(n0 + row) * (HW / 2) + (kbase >> 1) + j * 4;
            *(uint4*)(smem + AV_A_HI + row * 144 + j * 16) = *(const uint4*)(Hp + off);
        }
        // ---- stage B: bottomT scaled by s(k-strip), bf16-split in regs ----
        float s = fexp(g_tmax[b][trow + (kbase >> 7)] - gmax);
        #pragma unroll
        for (int it = 0; it < 4; it++) {
            int idx = tid + it * 256;              // 1024: k(64) x j(16)
            int k = idx >> 4, j = idx & 15;
            float4 v = *(const float4*)(BT + (kbase + k) * CC + 4 * j);
            v.x *= s; v.y *= s; v.z *= s; v.w *= s;
            unsigned hi[2], lo[2];
            cvt4(v, hi, lo);
            *(uint2*)(smem + AV_B_HI + k * 144 + j * 8) = make_uint2(hi[0], hi[1]);
            *(uint2*)(smem + AV_B_LO + k * 144 + j * 8) = make_uint2(lo[0], lo[1]);
        }
        __syncthreads();
        // ---- 4 k-steps of 16 ----
        #pragma unroll
        for (int k8 = 0; k8 < 4; k8++) {
            int k0 = k8 * 16;
            unsigned ah[2][4];
            #pragma unroll
            for (int mt = 0; mt < 2; mt++)
                ldsm_x4(ah[mt], sb + AV_A_HI + (arow + mt * 16) * 144 + (k0 + acolB) * 2);
            unsigned bh[4][2], bl[4][2];
            #pragma unroll
            for (int nt = 0; nt < 4; nt++) {
                unsigned baddr = sb + AV_B_HI + (k0 + bkrow) * 144 + (wc + nt * 8) * 2;
                ldsm_x2t(bh[nt], baddr);
                ldsm_x2t(bl[nt], baddr + (AV_B_LO - AV_B_HI));
            }
            #pragma unroll
            for (int mt = 0; mt < 2; mt++)
                #pragma unroll
                for (int nt = 0; nt < 4; nt++) {
                    mma_bf16(acc[mt][nt], ah[mt], bh[nt]);
                    mma_bf16(acc[mt][nt], ah[mt], bl[nt]);
                }
        }
        __syncthreads();
    }

    // ---- epilogue: / gsum, write split-K partial ----
    float inv = 1.0f / g_sum[b];
    float* O = g_spv[ks] + b * (HW * CC);
    int rbase = n0 + wn + (lid >> 2);
    int cbase = wc + (lid & 3) * 2;
    #pragma unroll
    for (int mt = 0; mt < 2; mt++)
        #pragma unroll
        for (int nt = 0; nt < 4; nt++) {
            int cc = cbase + nt * 8;
            *(float2*)(O + (rbase + mt * 16) * CC + cc) =
                make_float2(acc[mt][nt][0] * inv, acc[mt][nt][1] * inv);
            *(float2*)(O + (rbase + mt * 16 + 8) * CC + cc) =
                make_float2(acc[mt][nt][2] * inv, acc[mt][nt][3] * inv);
        }
}

// ---------------- launch ----------------
extern "C" void kernel_launch(void* const* d_in, const int* in_sizes, int n_in,
                              void* d_out, int out_size) {
    (void)in_sizes; (void)n_in; (void)out_size;
    const float* x     = (const float*)d_in[0];
    const float* top_w = (const float*)d_in[1];
    const float* top_b = (const float*)d_in[2];
    const float* cen_w = (const float*)d_in[3];
    const float* cen_b = (const float*)d_in[4];
    const float* bot_w = (const float*)d_in[5];
    const float* bot_b = (const float*)d_in[6];
    const float* out_w = (const float*)d_in[7];
    const float* out_b = (const float*)d_in[8];
    float* out = (float*)d_out;

    cudaFuncSetAttribute(k_qk_mma, cudaFuncAttributeMaxDynamicSharedMemorySize, SMEM_QK);
    cudaFuncSetAttribute(k_av_mma, cudaFuncAttributeMaxDynamicSharedMemorySize, SMEM_AV);

    k_proj<<<dim3(64, 4), 256>>>(x, top_w, top_b, cen_w, cen_b);
    k_conv3<false><<<dim3(32, 4), 512>>>(bot_w, bot_b, x, nullptr);
    k_qk_mma<<<dim3(32, 32, 4), 256, SMEM_QK>>>();
    k_combine<<<4, 1024>>>();
    k_av_mma<<<dim3(32, 2, 4), 256, SMEM_AV>>>();
    k_conv3<true><<<dim3(32, 4), 512>>>(out_w, out_b, x, out);
}

// round 15
// speedup vs baseline: 1.0006x; 1.0006x over previous
#include <cuda_runtime.h>
#include <cuda_bf16.h>
#include <math.h>

// ---------------- problem constants ----------------
#define BB  4
#define CC  64
#define HH  64
#define WW  64
#define HW  4096      // 64*64
#define KCH 192       // C*Q
#define PP  64
#define NTILE 1024    // 32x32 sp tiles per batch

typedef unsigned long long u64;

// ---------------- scratch (no allocations allowed) ----------------
__device__ __align__(128) float g_top[BB * PP * HW];        // (b,p,n)
__device__ __align__(128) float g_centerT[BB * HW * PP];    // (b,n,p)
__device__ __align__(128) float g_bottomT[BB * HW * CC];    // (b,m,c)
// exp(sp - tile_max) as ONE bf16 plane, packed 2 cols per u32 (denominator uses
// the SAME rounded values, so dominant-term rounding cancels in the softmax).
__device__ __align__(128) unsigned g_sph[(size_t)BB * HW * HW / 2];  // 134MB
__device__ __align__(128) float g_spv[2][BB * HW * CC];     // split-K partials
__device__ __align__(128) float g_tmax[BB][NTILE];
__device__ __align__(128) float g_tsum[BB][NTILE];
__device__ float g_max[BB];
__device__ float g_sum[BB];

// ---------------- packed f32x2 helpers ----------------
__device__ __forceinline__ u64 pk2(float lo, float hi) {
    u64 r; asm("mov.b64 %0,{%1,%2};" : "=l"(r) : "f"(lo), "f"(hi)); return r;
}
__device__ __forceinline__ u64 dup2(float a) { return pk2(a, a); }
__device__ __forceinline__ void up2(u64 v, float& lo, float& hi) {
    asm("mov.b64 {%0,%1},%2;" : "=f"(lo), "=f"(hi) : "l"(v));
}
__device__ __forceinline__ u64 fma2(u64 a, u64 b, u64 c) {
    u64 d; asm("fma.rn.f32x2 %0,%1,%2,%3;" : "=l"(d) : "l"(a), "l"(b), "l"(c)); return d;
}
__device__ __forceinline__ u64 mul2(u64 a, u64 b) {
    u64 d; asm("mul.rn.f32x2 %0,%1,%2;" : "=l"(d) : "l"(a), "l"(b)); return d;
}
__device__ __forceinline__ u64 add2(u64 a, u64 b) {
    u64 d; asm("add.rn.f32x2 %0,%1,%2;" : "=l"(d) : "l"(a), "l"(b)); return d;
}

// FMA-pipe exp (scalar), x <= 0 expected, clamped at -80.
__device__ __forceinline__ float fexp(float x) {
    x = fmaxf(x, -80.0f);
    float t = x * 1.4426950408889634f;
    float n = rintf(t);
    float f = t - n;
    float p = 1.5403530e-4f;
    p = fmaf(p, f, 1.3333558e-3f);
    p = fmaf(p, f, 9.6181291e-3f);
    p = fmaf(p, f, 5.5504109e-2f);
    p = fmaf(p, f, 2.4022651e-1f);
    p = fmaf(p, f, 6.9314718e-1f);
    p = fmaf(p, f, 1.0f);
    int e = (int)n;
    return p * __int_as_float((e + 127) << 23);
}

// packed exp2-based exp(x - off): caller folds offset into TOFF
__device__ __forceinline__ u64 fexp2pair(u64 x2, u64 L2E, u64 TOFF,
                                         u64 MAGIC, u64 NMAG, u64 NEG1,
                                         u64 C6, u64 C5, u64 C4, u64 C3,
                                         u64 C2, u64 C1, u64 ONE) {
    u64 t  = fma2(x2, L2E, TOFF);
    u64 z  = add2(t, MAGIC);
    u64 nf = add2(z, NMAG);
    u64 f  = fma2(nf, NEG1, t);
    u64 p  = fma2(C6, f, C5);
    p = fma2(p, f, C4); p = fma2(p, f, C3);
    p = fma2(p, f, C2); p = fma2(p, f, C1);
    p = fma2(p, f, ONE);
    unsigned zl, zh;
    asm("mov.b64 {%0,%1},%2;" : "=r"(zl), "=r"(zh) : "l"(z));
    int el = max((int)zl - 0x4B400000, -126) + 127;
    int eh = max((int)zh - 0x4B400000, -126) + 127;
    u64 s = pk2(__int_as_float(el << 23), __int_as_float(eh << 23));
    return mul2(p, s);
}

// ---------------- mma.sync / ldmatrix helpers (baseline PTX) ----------------
__device__ __forceinline__ void ldsm_x4(unsigned* r, unsigned a) {
    asm volatile("ldmatrix.sync.aligned.m8n8.x4.shared.b16 {%0,%1,%2,%3}, [%4];"
        : "=r"(r[0]), "=r"(r[1]), "=r"(r[2]), "=r"(r[3]) : "r"(a));
}
__device__ __forceinline__ void ldsm_x2t(unsigned* r, unsigned a) {
    asm volatile("ldmatrix.sync.aligned.m8n8.x2.trans.shared.b16 {%0,%1}, [%2];"
        : "=r"(r[0]), "=r"(r[1]) : "r"(a));
}
__device__ __forceinline__ void mma_bf16(float* d, const unsigned* a, const unsigned* b) {
    asm volatile("mma.sync.aligned.m16n8k16.row.col.f32.bf16.bf16.f32 "
        "{%0,%1,%2,%3}, {%4,%5,%6,%7}, {%8,%9}, {%0,%1,%2,%3};"
        : "+f"(d[0]), "+f"(d[1]), "+f"(d[2]), "+f"(d[3])
        : "r"(a[0]), "r"(a[1]), "r"(a[2]), "r"(a[3]), "r"(b[0]), "r"(b[1]));
}

// split one float4 into hi/lo bf16x2 pairs
__device__ __forceinline__ void cvt4(float4 v, unsigned* hi, unsigned* lo) {
    float a[4] = {v.x, v.y, v.z, v.w};
    #pragma unroll
    for (int p = 0; p < 2; p++) {
        __nv_bfloat162 h = __floats2bfloat162_rn(a[2*p], a[2*p+1]);
        float2 f = __bfloat1622float2(h);
        __nv_bfloat162 l = __floats2bfloat162_rn(a[2*p] - f.x, a[2*p+1] - f.y);
        hi[p] = *(unsigned*)&h;
        lo[p] = *(unsigned*)&l;
    }
}

// ---------------- K2: 1x1 SelfONN convs (top & center), powers inline ----------------
// (scalar-FFMA version: the FFMA2 variant spilled and regressed 250us in R14)
__global__ void k_proj(const float* __restrict__ x,
                       const float* __restrict__ top_w, const float* __restrict__ top_b,
                       const float* __restrict__ cen_w, const float* __restrict__ cen_b) {
    __shared__ __align__(16) float As_t[32 * 68];
    __shared__ __align__(16) float As_c[32 * 68];
    __shared__ __align__(16) float Bs[32 * 64];
    int b  = blockIdx.y;
    int n0 = blockIdx.x * 64;
    int tid = threadIdx.x;
    int p0 = (tid >> 4) * 4;
    int j0 = (tid & 15) * 4;
    float at[4][4] = {}, ac[4][4] = {};

    for (int kc = 0; kc < KCH; kc += 32) {
        int q = kc >> 6;
        #pragma unroll
        for (int it = 0; it < 2; it++) {
            int f4 = tid + it * 256;
            int p = f4 >> 3, k4 = f4 & 7;
            float4 vt = *(const float4*)(top_w + p * KCH + kc + 4 * k4);
            float4 vc = *(const float4*)(cen_w + p * KCH + kc + 4 * k4);
            As_t[(4*k4+0)*68 + p] = vt.x; As_t[(4*k4+1)*68 + p] = vt.y;
            As_t[(4*k4+2)*68 + p] = vt.z; As_t[(4*k4+3)*68 + p] = vt.w;
            As_c[(4*k4+0)*68 + p] = vc.x; As_c[(4*k4+1)*68 + p] = vc.y;
            As_c[(4*k4+2)*68 + p] = vc.z; As_c[(4*k4+3)*68 + p] = vc.w;
        }
        #pragma unroll
        for (int it = 0; it < 2; it++) {
            int f4 = tid + it * 256;
            int k = f4 >> 4, j4 = f4 & 15;
            int c = (kc + k) & 63;
            float4 v = *(const float4*)(x + ((b * CC + c) << 12) + n0 + 4 * j4);
            if (q >= 1) { v.x *= v.x ; v.y *= v.y ; v.z *= v.z ; v.w *= v.w; }
            if (q == 2) {
                float4 v1 = *(const float4*)(x + ((b * CC + c) << 12) + n0 + 4 * j4);
                v.x *= v1.x; v.y *= v1.y; v.z *= v1.z; v.w *= v1.w;
            }
            *(float4*)(Bs + k * 64 + 4 * j4) = v;
        }
        __syncthreads();
        #pragma unroll 8
        for (int k = 0; k < 32; k++) {
            float a1[4]; *(float4*)a1 = *(float4*)(As_t + k * 68 + p0);
            float a2[4]; *(float4*)a2 = *(float4*)(As_c + k * 68 + p0);
            float bv[4]; *(float4*)bv = *(float4*)(Bs  + k * 64 + j0);
            #pragma unroll
            for (int u = 0; u < 4; u++)
                #pragma unroll
                for (int v = 0; v < 4; v++) {
                    at[u][v] = fmaf(a1[u], bv[v], at[u][v]);
                    ac[u][v] = fmaf(a2[u], bv[v], ac[u][v]);
                }
        }
        __syncthreads();
    }
    #pragma unroll
    for (int u = 0; u < 4; u++) {
        float bt = top_b[p0 + u], bc = cen_b[p0 + u];
        float4 o;
        o.x = at[u][0] + bt; o.y = at[u][1] + bt; o.z = at[u][2] + bt; o.w = at[u][3] + bt;
        *(float4*)(g_top + b * (PP * HW) + (p0 + u) * HW + n0 + j0) = o;
        #pragma unroll
        for (int v = 0; v < 4; v++)
            g_centerT[b * (HW * PP) + (n0 + j0 + v) * PP + p0 + u] = ac[u][v] + bc;
    }
}

// ---------------- K3/K7: 3x3 SelfONN conv, chunked implicit GEMM, FFMA2 ----------------
template <bool FINAL>
__global__ void __launch_bounds__(512, 2)
k_conv3(const float* __restrict__ w, const float* __restrict__ bias,
        const float* __restrict__ x, float* __restrict__ out) {
    __shared__ __align__(16) float s_in[8 * 4 * 68];
    __shared__ __align__(16) float s_w[72 * 68];
    int b   = blockIdx.y;
    int h0  = blockIdx.x * 2;
    int tid = threadIdx.x;
    int g    = tid & 31;
    int r    = g >> 4;
    int col0 = (g & 15) * 4;
    int oc0  = (tid >> 5) * 4;
    u64 acc[2][4];
    #pragma unroll
    for (int p = 0; p < 2; p++)
        #pragma unroll
        for (int v = 0; v < 4; v++) acc[p][v] = 0ull;

    for (int kc = 0; kc < KCH; kc += 8) {
        int qi    = kc >> 6;
        int cbase = kc & 63;
        #pragma unroll
        for (int it = 0; it < 5; it++) {
            int idx = tid + it * 512;
            if (idx < 8 * 4 * 68) {
                int c   = idx / 272;
                int rem = idx - c * 272;
                int rr  = rem / 68;
                int ic  = rem - rr * 68;
                int gh = h0 - 1 + rr;
                int gw = ic - 1;
                float v = 0.0f;
                if ((unsigned)gh < HH && (unsigned)gw < WW) {
                    int gidx = ((b * CC + cbase + c) << 12) + (gh << 6) + gw;
                    float y = x[gidx];
                    if (FINAL) y += g_spv[0][gidx] + g_spv[1][gidx];
                    v = y;
                    if (qi >= 1) v *= y;
                    if (qi == 2) v *= y;
                }
                s_in[idx] = v;
            }
        }
        #pragma unroll
        for (int it = 0; it < 9; it++) {
            int i = tid + it * 512;
            int oc  = i / 72;
            int rem = i - oc * 72;
            s_w[rem * 68 + oc] = w[(oc * KCH + kc) * 9 + rem];
        }
        __syncthreads();
        #pragma unroll
        for (int c = 0; c < 8; c++) {
            #pragma unroll
            for (int dy = 0; dy < 3; dy++) {
                const float* rowp = s_in + c * 272 + (r + dy) * 68 + col0;
                float4 t0 = *(const float4*)rowp;
                float2 t1 = *(const float2*)(rowp + 4);
                u64 wd[6];
                wd[0] = dup2(t0.x); wd[1] = dup2(t0.y); wd[2] = dup2(t0.z);
                wd[3] = dup2(t0.w); wd[4] = dup2(t1.x); wd[5] = dup2(t1.y);
                #pragma unroll
                for (int dx = 0; dx < 3; dx++) {
                    ulonglong2 wp = *(const ulonglong2*)
                        (s_w + ((c * 3 + dy) * 3 + dx) * 68 + oc0);
                    #pragma unroll
                    for (int v = 0; v < 4; v++) {
                        acc[0][v] = fma2(wp.x, wd[dx + v], acc[0][v]);
                        acc[1][v] = fma2(wp.y, wd[dx + v], acc[1][v]);
                    }
                }
            }
        }
        __syncthreads();
    }

    float av[4][4];
    #pragma unroll
    for (int p = 0; p < 2; p++)
        #pragma unroll
        for (int v = 0; v < 4; v++)
            up2(acc[p][v], av[2*p][v], av[2*p+1][v]);
    float bs[4];
    #pragma unroll
    for (int u = 0; u < 4; u++) bs[u] = bias[oc0 + u];
    int px_row = (h0 + r) << 6;
    if (FINAL) {
        #pragma unroll
        for (int u = 0; u < 4; u++) {
            float4 o;
            o.x = av[u][0] + bs[u]; o.y = av[u][1] + bs[u];
            o.z = av[u][2] + bs[u]; o.w = av[u][3] + bs[u];
            *(float4*)(out + ((b * CC + oc0 + u) << 12) + px_row + col0) = o;
        }
    } else {
        #pragma unroll
        for (int v = 0; v < 4; v++) {
            float4 o;
            o.x = av[0][v] + bs[0]; o.y = av[1][v] + bs[1];
            o.z = av[2][v] + bs[2]; o.w = av[3][v] + bs[3];
            *(float4*)(g_bottomT + b * (HW * CC) + (px_row + col0 + v) * CC + oc0) = o;
        }
    }
}

// ---------------- K4: QK via mma.sync bf16-split + tile-local softmax ----------------
// Epilogue stores exp(sp - tmax) as ONE bf16 plane; tile sums use the ROUNDED values.
#define OFF_A_HI  128                       // [128 n][72 k] bf16 (144B rows)
#define OFF_A_LO  (OFF_A_HI + 128*144)
#define OFF_B_HI  (OFF_A_LO + 128*144)      // [64 k][136 m] bf16 (272B rows)
#define OFF_B_LO  (OFF_B_HI + 64*272)
#define SMEM_QK   (OFF_B_LO + 64*272)       // 71808 B

__global__ void __launch_bounds__(256, 2)
k_qk_mma() {
    extern __shared__ char smem[];
    unsigned sb;
    asm("{ .reg .u64 t; cvta.to.shared.u64 t, %1; cvt.u32.u64 %0, t; }"
        : "=r"(sb) : "l"(smem));
    int b  = blockIdx.z;
    int m0 = blockIdx.x * 128;
    int n0 = blockIdx.y * 128;
    int tid = threadIdx.x;
    int wid = tid >> 5, lid = tid & 31;
    float* s_red = (float*)smem;

    // ---- stage A (centerT rows, hi/lo) ----
    const float* Ag = g_centerT + (size_t)b * (HW * PP);
    #pragma unroll 2
    for (int it = 0; it < 8; it++) {
        int idx = tid + it * 256;          // 2048: n(128) x kf4(16)
        int n = idx >> 4, kf4 = idx & 15;
        float4 v = *(const float4*)(Ag + (n0 + n) * PP + 4 * kf4);
        unsigned hi[2], lo[2];
        cvt4(v, hi, lo);
        *(uint2*)(smem + OFF_A_HI + n * 144 + 8 * kf4) = make_uint2(hi[0], hi[1]);
        *(uint2*)(smem + OFF_A_LO + n * 144 + 8 * kf4) = make_uint2(lo[0], lo[1]);
    }
    // ---- stage B (top rows [k][m], hi/lo) ----
    const float* Bg = g_top + (size_t)b * (PP * HW) + m0;
    #pragma unroll 2
    for (int it = 0; it < 8; it++) {
        int idx = tid + it * 256;          // 2048: k(64) x mf4(32)
        int k = idx >> 5, mf4 = idx & 31;
        float4 v = *(const float4*)(Bg + k * HW + 4 * mf4);
        unsigned hi[2], lo[2];
        cvt4(v, hi, lo);
        *(uint2*)(smem + OFF_B_HI + k * 272 + 8 * mf4) = make_uint2(hi[0], hi[1]);
        *(uint2*)(smem + OFF_B_LO + k * 272 + 8 * mf4) = make_uint2(lo[0], lo[1]);
    }
    __syncthreads();

    // ---- warp tiling: warp_n = wid>>1 (4 x 32 rows), warp_m = wid&1 (2 x 64 cols) ----
    int wn = (wid >> 1) * 32;
    int wm = (wid & 1) * 64;
    float acc[2][8][4];
    #pragma unroll
    for (int mt = 0; mt < 2; mt++)
        #pragma unroll
        for (int nt = 0; nt < 8; nt++)
            #pragma unroll
            for (int e = 0; e < 4; e++) acc[mt][nt][e] = 0.0f;

    int arow = wn + (lid & 15);
    int acolB = (lid >> 4) * 8;
    int bkrow = (lid & 15);

    #pragma unroll
    for (int ks = 0; ks < 4; ks++) {
        int k0 = ks * 16;
        unsigned ah[2][4], al[2][4];
        #pragma unroll
        for (int mt = 0; mt < 2; mt++) {
            unsigned aaddr = sb + OFF_A_HI + (arow + mt * 16) * 144 + (k0 + acolB) * 2;
            ldsm_x4(ah[mt], aaddr);
            ldsm_x4(al[mt], aaddr + (OFF_A_LO - OFF_A_HI));
        }
        unsigned bf[8][2];
        #pragma unroll
        for (int nt = 0; nt < 8; nt++)
            ldsm_x2t(bf[nt], sb + OFF_B_HI + (k0 + bkrow) * 272 + (wm + nt * 8) * 2);
        #pragma unroll
        for (int mt = 0; mt < 2; mt++)
            #pragma unroll
            for (int nt = 0; nt < 8; nt++) {
                mma_bf16(acc[mt][nt], ah[mt], bf[nt]);
                mma_bf16(acc[mt][nt], al[mt], bf[nt]);
            }
        #pragma unroll
        for (int nt = 0; nt < 8; nt++)
            ldsm_x2t(bf[nt], sb + OFF_B_LO + (k0 + bkrow) * 272 + (wm + nt * 8) * 2);
        #pragma unroll
        for (int mt = 0; mt < 2; mt++)
            #pragma unroll
            for (int nt = 0; nt < 8; nt++)
                mma_bf16(acc[mt][nt], ah[mt], bf[nt]);
    }

    // ---- tile max (block-wide) ----
    float mx = -INFINITY;
    #pragma unroll
    for (int mt = 0; mt < 2; mt++)
        #pragma unroll
        for (int nt = 0; nt < 8; nt++)
            #pragma unroll
            for (int e = 0; e < 4; e++)
                mx = fmaxf(mx, acc[mt][nt][e]);
    #pragma unroll
    for (int off = 16; off > 0; off >>= 1)
        mx = fmaxf(mx, __shfl_xor_sync(0xffffffffu, mx, off));
    if (lid == 0) s_red[wid] = mx;
    __syncthreads();
    float tmax = s_red[0];
    #pragma unroll
    for (int i = 1; i < 8; i++) tmax = fmaxf(tmax, s_red[i]);

    // ---- packed exp(sp - tmax) -> bf16, sum the ROUNDED values, store ----
    const u64 L2E   = dup2(1.4426950408889634f);
    const u64 TOFF  = dup2(-tmax * 1.4426950408889634f);
    const u64 MAGIC = dup2(12582912.0f);
    const u64 NMAG  = dup2(-12582912.0f);
    const u64 NEG1  = dup2(-1.0f);
    const u64 C6 = dup2(1.5403530e-4f), C5 = dup2(1.3333558e-3f);
    const u64 C4 = dup2(9.6181291e-3f), C3 = dup2(5.5504109e-2f);
    const u64 C2 = dup2(2.4022651e-1f), C1 = dup2(6.9314718e-1f);
    const u64 ONE = dup2(1.0f);
    float ssum = 0.0f;
    unsigned* Ho = g_sph + ((size_t)b << 23);
    int rbase = n0 + wn + (lid >> 2);
    int cbase = m0 + wm + (lid & 3) * 2;
    #pragma unroll
    for (int mt = 0; mt < 2; mt++)
        #pragma unroll
        for (int nt = 0; nt < 8; nt++) {
            u64 e01 = fexp2pair(pk2(acc[mt][nt][0], acc[mt][nt][1]),
                                L2E, TOFF, MAGIC, NMAG, NEG1,
                                C6, C5, C4, C3, C2, C1, ONE);
            u64 e23 = fexp2pair(pk2(acc[mt][nt][2], acc[mt][nt][3]),
                                L2E, TOFF, MAGIC, NMAG, NEG1,
                                C6, C5, C4, C3, C2, C1, ONE);
            float e0, e1, e2, e3;
            up2(e01, e0, e1); up2(e23, e2, e3);
            __nv_bfloat162 h01 = __floats2bfloat162_rn(e0, e1);
            __nv_bfloat162 h23 = __floats2bfloat162_rn(e2, e3);
            float2 f0 = __bfloat1622float2(h01);
            float2 f1 = __bfloat1622float2(h23);
            ssum += (f0.x + f0.y) + (f1.x + f1.y);
            int cc = cbase + nt * 8;
            Ho[((size_t)(rbase + mt * 16) * HW + cc) >> 1] = *(unsigned*)&h01;
            Ho[((size_t)(rbase + mt * 16 + 8) * HW + cc) >> 1] = *(unsigned*)&h23;
        }
    #pragma unroll
    for (int off = 16; off > 0; off >>= 1)
        ssum += __shfl_xor_sync(0xffffffffu, ssum, off);
    __syncthreads();
    if (lid == 0) s_red[wid] = ssum;
    __syncthreads();
    if (tid == 0) {
        float t = 0.0f;
        #pragma unroll
        for (int i = 0; i < 8; i++) t += s_red[i];
        int tile = blockIdx.y * 32 + blockIdx.x;
        g_tmax[b][tile] = tmax;
        g_tsum[b][tile] = t;
    }
}

// ---------------- K5: combine per-tile (max,sum) -> global (max,sum) ----------------
__global__ void k_combine() {
    int b = blockIdx.x;
    int tid = threadIdx.x;               // 1024 threads, one per tile
    __shared__ float s_red[32];
    float v = g_tmax[b][tid];
    float mx = v;
    #pragma unroll
    for (int off = 16; off > 0; off >>= 1)
        mx = fmaxf(mx, __shfl_xor_sync(0xffffffffu, mx, off));
    if ((tid & 31) == 0) s_red[tid >> 5] = mx;
    __syncthreads();
    if (tid < 32) {
        float m2 = s_red[tid];
        #pragma unroll
        for (int off = 16; off > 0; off >>= 1)
            m2 = fmaxf(m2, __shfl_xor_sync(0xffffffffu, m2, off));
        if (tid == 0) s_red[0] = m2;
    }
    __syncthreads();
    float gmax = s_red[0];
    __syncthreads();
    float part = g_tsum[b][tid] * fexp(v - gmax);
    #pragma unroll
    for (int off = 16; off > 0; off >>= 1)
        part += __shfl_xor_sync(0xffffffffu, part, off);
    __shared__ float s_sum[32];
    if ((tid & 31) == 0) s_sum[tid >> 5] = part;
    __syncthreads();
    if (tid < 32) {
        float t = s_sum[tid];
        #pragma unroll
        for (int off = 16; off > 0; off >>= 1)
            t += __shfl_xor_sync(0xffffffffu, t, off);
        if (tid == 0) { g_max[b] = gmax; g_sum[b] = t; }
    }
}

// ---------------- K6: spv = E @ bottomT via mma.sync (E bf16, B split), split-K 2 ----
#define AV_A_HI 0                           // [128 n][72 k] bf16 (144B rows)
#define AV_B_HI (AV_A_HI + 128*144)         // [64 k][72 c] bf16 (144B rows)
#define AV_B_LO (AV_B_HI + 64*144)
#define SMEM_AV (AV_B_LO + 64*144)          // 36864 B

__global__ void __launch_bounds__(256, 3)
k_av_mma() {
    extern __shared__ char smem[];
    unsigned sb;
    asm("{ .reg .u64 t; cvta.to.shared.u64 t, %1; cvt.u32.u64 %0, t; }"
        : "=r"(sb) : "l"(smem));
    int b  = blockIdx.z;
    int ks = blockIdx.y;
    int n0 = blockIdx.x * 128;
    int tid = threadIdx.x;
    int wid = tid >> 5, lid = tid & 31;
    int wn = (wid >> 1) * 32;       // warp rows
    int wc = (wid & 1) * 32;        // warp cols
    const unsigned* Hp = g_sph + ((size_t)b << 23);
    const float* BT = g_bottomT + b * (HW * CC);
    float gmax = g_max[b];
    int trow = (n0 >> 7) * 32;

    float acc[2][4][4];
    #pragma unroll
    for (int mt = 0; mt < 2; mt++)
        #pragma unroll
        for (int nt = 0; nt < 4; nt++)
            #pragma unroll
            for (int e = 0; e < 4; e++) acc[mt][nt][e] = 0.0f;

    int arow = wn + (lid & 15);
    int acolB = (lid >> 4) * 8;
    int bkrow = (lid & 15);

    for (int kc = 0; kc < 2048; kc += 64) {
        int kbase = ks * 2048 + kc;
        // ---- stage A: bf16 E plane straight from gmem ----
        #pragma unroll
        for (int it = 0; it < 4; it++) {
            int idx = tid + it * 256;              // 1024: row(128) x j(8)
            int row = idx >> 3, j = idx & 7;
            size_t off = (size_t)(n0 + row) * (HW / 2) + (kbase >> 1) + j * 4;
            *(uint4*)(smem + AV_A_HI + row * 144 + j * 16) = *(const uint4*)(Hp + off);
        }
        // ---- stage B: bottomT scaled by s(k-strip), bf16-split in regs ----
        float s = fexp(g_tmax[b][trow + (kbase >> 7)] - gmax);
        #pragma unroll
        for (int it = 0; it < 4; it++) {
            int idx = tid + it * 256;              // 1024: k(64) x j(16)
            int k = idx >> 4, j = idx & 15;
            float4 v = *(const float4*)(BT + (kbase + k) * CC + 4 * j);
            v.x *= s; v.y *= s; v.z *= s; v.w *= s;
            unsigned hi[2], lo[2];
            cvt4(v, hi, lo);
            *(uint2*)(smem + AV_B_HI + k * 144 + j * 8) = make_uint2(hi[0], hi[1]);
            *(uint2*)(smem + AV_B_LO + k * 144 + j * 8) = make_uint2(lo[0], lo[1]);
        }
        __syncthreads();
        // ---- 4 k-steps of 16 ----
        #pragma unroll
        for (int k8 = 0; k8 < 4; k8++) {
            int k0 = k8 * 16;
            unsigned ah[2][4];
            #pragma unroll
            for (int mt = 0; mt < 2; mt++)
                ldsm_x4(ah[mt], sb + AV_A_HI + (arow + mt * 16) * 144 + (k0 + acolB) * 2);
            unsigned bh[4][2], bl[4][2];
            #pragma unroll
            for (int nt = 0; nt < 4; nt++) {
                unsigned baddr = sb + AV_B_HI + (k0 + bkrow) * 144 + (wc + nt * 8) * 2;
                ldsm_x2t(bh[nt], baddr);
                ldsm_x2t(bl[nt], baddr + (AV_B_LO - AV_B_HI));
            }
            #pragma unroll
            for (int mt = 0; mt < 2; mt++)
                #pragma unroll
                for (int nt = 0; nt < 4; nt++) {
                    mma_bf16(acc[mt][nt], ah[mt], bh[nt]);
                    mma_bf16(acc[mt][nt], ah[mt], bl[nt]);
                }
        }
        __syncthreads();
    }

    // ---- epilogue: / gsum, write split-K partial ----
    float inv = 1.0f / g_sum[b];
    float* O = g_spv[ks] + b * (HW * CC);
    int rbase = n0 + wn + (lid >> 2);
    int cbase = wc + (lid & 3) * 2;
    #pragma unroll
    for (int mt = 0; mt < 2; mt++)
        #pragma unroll
        for (int nt = 0; nt < 4; nt++) {
            int cc = cbase + nt * 8;
            *(float2*)(O + (rbase + mt * 16) * CC + cc) =
                make_float2(acc[mt][nt][0] * inv, acc[mt][nt][1] * inv);
            *(float2*)(O + (rbase + mt * 16 + 8) * CC + cc) =
                make_float2(acc[mt][nt][2] * inv, acc[mt][nt][3] * inv);
        }
}

// ---------------- launch ----------------
extern "C" void kernel_launch(void* const* d_in, const int* in_sizes, int n_in,
                              void* d_out, int out_size) {
    (void)in_sizes; (void)n_in; (void)out_size;
    const float* x     = (const float*)d_in[0];
    const float* top_w = (const float*)d_in[1];
    const float* top_b = (const float*)d_in[2];
    const float* cen_w = (const float*)d_in[3];
    const float* cen_b = (const float*)d_in[4];
    const float* bot_w = (const float*)d_in[5];
    const float* bot_b = (const float*)d_in[6];
    const float* out_w = (const float*)d_in[7];
    const float* out_b = (const float*)d_in[8];
    float* out = (float*)d_out;

    cudaFuncSetAttribute(k_qk_mma, cudaFuncAttributeMaxDynamicSharedMemorySize, SMEM_QK);
    cudaFuncSetAttribute(k_av_mma, cudaFuncAttributeMaxDynamicSharedMemorySize, SMEM_AV);

    k_proj<<<dim3(64, 4), 256>>>(x, top_w, top_b, cen_w, cen_b);
    k_conv3<false><<<dim3(32, 4), 512>>>(bot_w, bot_b, x, nullptr);
    k_qk_mma<<<dim3(32, 32, 4), 256, SMEM_QK>>>();
    k_combine<<<4, 1024>>>();
    k_av_mma<<<dim3(32, 2, 4), 256, SMEM_AV>>>();
    k_conv3<true><<<dim3(32, 4), 512>>>(out_w, out_b, x, out);
}

// round 16
// speedup vs baseline: 1.4081x; 1.4073x over previous
#include <cuda_runtime.h>
#include <cuda_bf16.h>
#include <math.h>

// ---------------- problem constants ----------------
#define BB  4
#define CC  64
#define HH  64
#define WW  64
#define HW  4096      // 64*64
#define KCH 192       // C*Q
#define PP  64
#define NTILE 1024    // 32x32 sp tiles per batch

typedef unsigned long long u64;

// ---------------- scratch (no allocations allowed) ----------------
__device__ __align__(128) float g_top[BB * PP * HW];        // (b,p,n)
__device__ __align__(128) float g_centerT[BB * HW * PP];    // (b,n,p)
__device__ __align__(128) float g_bottomT[BB * HW * CC];    // (b,m,c)
// exp(sp - tile_max) as ONE bf16 plane, packed 2 cols per u32 (denominator uses
// the SAME rounded values, so dominant-term rounding cancels in the softmax).
__device__ __align__(128) unsigned g_sph[(size_t)BB * HW * HW / 2];  // 134MB
__device__ __align__(128) float g_spv[2][BB * HW * CC];     // split-K partials
__device__ __align__(128) float g_tmax[BB][NTILE];
__device__ __align__(128) float g_tsum[BB][NTILE];
__device__ float g_max[BB];
__device__ float g_sum[BB];

// ---------------- packed f32x2 helpers ----------------
__device__ __forceinline__ u64 pk2(float lo, float hi) {
    u64 r; asm("mov.b64 %0,{%1,%2};" : "=l"(r) : "f"(lo), "f"(hi)); return r;
}
__device__ __forceinline__ u64 dup2(float a) { return pk2(a, a); }
__device__ __forceinline__ void up2(u64 v, float& lo, float& hi) {
    asm("mov.b64 {%0,%1},%2;" : "=f"(lo), "=f"(hi) : "l"(v));
}
__device__ __forceinline__ u64 fma2(u64 a, u64 b, u64 c) {
    u64 d; asm("fma.rn.f32x2 %0,%1,%2,%3;" : "=l"(d) : "l"(a), "l"(b), "l"(c)); return d;
}
__device__ __forceinline__ u64 mul2(u64 a, u64 b) {
    u64 d; asm("mul.rn.f32x2 %0,%1,%2;" : "=l"(d) : "l"(a), "l"(b)); return d;
}
__device__ __forceinline__ u64 add2(u64 a, u64 b) {
    u64 d; asm("add.rn.f32x2 %0,%1,%2;" : "=l"(d) : "l"(a), "l"(b)); return d;
}

// FMA-pipe exp (scalar), x <= 0 expected, clamped at -80.
__device__ __forceinline__ float fexp(float x) {
    x = fmaxf(x, -80.0f);
    float t = x * 1.4426950408889634f;
    float n = rintf(t);
    float f = t - n;
    float p = 1.5403530e-4f;
    p = fmaf(p, f, 1.3333558e-3f);
    p = fmaf(p, f, 9.6181291e-3f);
    p = fmaf(p, f, 5.5504109e-2f);
    p = fmaf(p, f, 2.4022651e-1f);
    p = fmaf(p, f, 6.9314718e-1f);
    p = fmaf(p, f, 1.0f);
    int e = (int)n;
    return p * __int_as_float((e + 127) << 23);
}

// packed exp2-based exp(x - off): caller folds offset into TOFF
__device__ __forceinline__ u64 fexp2pair(u64 x2, u64 L2E, u64 TOFF,
                                         u64 MAGIC, u64 NMAG, u64 NEG1,
                                         u64 C6, u64 C5, u64 C4, u64 C3,
                                         u64 C2, u64 C1, u64 ONE) {
    u64 t  = fma2(x2, L2E, TOFF);
    u64 z  = add2(t, MAGIC);
    u64 nf = add2(z, NMAG);
    u64 f  = fma2(nf, NEG1, t);
    u64 p  = fma2(C6, f, C5);
    p = fma2(p, f, C4); p = fma2(p, f, C3);
    p = fma2(p, f, C2); p = fma2(p, f, C1);
    p = fma2(p, f, ONE);
    unsigned zl, zh;
    asm("mov.b64 {%0,%1},%2;" : "=r"(zl), "=r"(zh) : "l"(z));
    int el = max((int)zl - 0x4B400000, -126) + 127;
    int eh = max((int)zh - 0x4B400000, -126) + 127;
    u64 s = pk2(__int_as_float(el << 23), __int_as_float(eh << 23));
    return mul2(p, s);
}

// ---------------- mma.sync / ldmatrix helpers (baseline PTX) ----------------
__device__ __forceinline__ void ldsm_x4(unsigned* r, unsigned a) {
    asm volatile("ldmatrix.sync.aligned.m8n8.x4.shared.b16 {%0,%1,%2,%3}, [%4];"
        : "=r"(r[0]), "=r"(r[1]), "=r"(r[2]), "=r"(r[3]) : "r"(a));
}
__device__ __forceinline__ void ldsm_x2t(unsigned* r, unsigned a) {
    asm volatile("ldmatrix.sync.aligned.m8n8.x2.trans.shared.b16 {%0,%1}, [%2];"
        : "=r"(r[0]), "=r"(r[1]) : "r"(a));
}
__device__ __forceinline__ void mma_bf16(float* d, const unsigned* a, const unsigned* b) {
    asm volatile("mma.sync.aligned.m16n8k16.row.col.f32.bf16.bf16.f32 "
        "{%0,%1,%2,%3}, {%4,%5,%6,%7}, {%8,%9}, {%0,%1,%2,%3};"
        : "+f"(d[0]), "+f"(d[1]), "+f"(d[2]), "+f"(d[3])
        : "r"(a[0]), "r"(a[1]), "r"(a[2]), "r"(a[3]), "r"(b[0]), "r"(b[1]));
}

// split one float4 into hi/lo bf16x2 pairs
__device__ __forceinline__ void cvt4(float4 v, unsigned* hi, unsigned* lo) {
    float a[4] = {v.x, v.y, v.z, v.w};
    #pragma unroll
    for (int p = 0; p < 2; p++) {
        __nv_bfloat162 h = __floats2bfloat162_rn(a[2*p], a[2*p+1]);
        float2 f = __bfloat1622float2(h);
        __nv_bfloat162 l = __floats2bfloat162_rn(a[2*p] - f.x, a[2*p+1] - f.y);
        hi[p] = *(unsigned*)&h;
        lo[p] = *(unsigned*)&l;
    }
}

// ---------------- K2: 1x1 SelfONN convs (top & center), powers inline ----------------
__global__ void k_proj(const float* __restrict__ x,
                       const float* __restrict__ top_w, const float* __restrict__ top_b,
                       const float* __restrict__ cen_w, const float* __restrict__ cen_b) {
    __shared__ __align__(16) float As_t[32 * 68];
    __shared__ __align__(16) float As_c[32 * 68];
    __shared__ __align__(16) float Bs[32 * 64];
    int b  = blockIdx.y;
    int n0 = blockIdx.x * 64;
    int tid = threadIdx.x;
    int p0 = (tid >> 4) * 4;
    int j0 = (tid & 15) * 4;
    float at[4][4] = {}, ac[4][4] = {};

    for (int kc = 0; kc < KCH; kc += 32) {
        int q = kc >> 6;
        #pragma unroll
        for (int it = 0; it < 2; it++) {
            int f4 = tid + it * 256;
            int p = f4 >> 3, k4 = f4 & 7;
            float4 vt = *(const float4*)(top_w + p * KCH + kc + 4 * k4);
            float4 vc = *(const float4*)(cen_w + p * KCH + kc + 4 * k4);
            As_t[(4*k4+0)*68 + p] = vt.x; As_t[(4*k4+1)*68 + p] = vt.y;
            As_t[(4*k4+2)*68 + p] = vt.z; As_t[(4*k4+3)*68 + p] = vt.w;
            As_c[(4*k4+0)*68 + p] = vc.x; As_c[(4*k4+1)*68 + p] = vc.y;
            As_c[(4*k4+2)*68 + p] = vc.z; As_c[(4*k4+3)*68 + p] = vc.w;
        }
        #pragma unroll
        for (int it = 0; it < 2; it++) {
            int f4 = tid + it * 256;
            int k = f4 >> 4, j4 = f4 & 15;
            int c = (kc + k) & 63;
            float4 v = *(const float4*)(x + ((b * CC + c) << 12) + n0 + 4 * j4);
            if (q >= 1) { v.x *= v.x ; v.y *= v.y ; v.z *= v.z ; v.w *= v.w; }
            if (q == 2) {
                float4 v1 = *(const float4*)(x + ((b * CC + c) << 12) + n0 + 4 * j4);
                v.x *= v1.x; v.y *= v1.y; v.z *= v1.z; v.w *= v1.w;
            }
            *(float4*)(Bs + k * 64 + 4 * j4) = v;
        }
        __syncthreads();
        #pragma unroll 8
        for (int k = 0; k < 32; k++) {
            float a1[4]; *(float4*)a1 = *(float4*)(As_t + k * 68 + p0);
            float a2[4]; *(float4*)a2 = *(float4*)(As_c + k * 68 + p0);
            float bv[4]; *(float4*)bv = *(float4*)(Bs  + k * 64 + j0);
            #pragma unroll
            for (int u = 0; u < 4; u++)
                #pragma unroll
                for (int v = 0; v < 4; v++) {
                    at[u][v] = fmaf(a1[u], bv[v], at[u][v]);
                    ac[u][v] = fmaf(a2[u], bv[v], ac[u][v]);
                }
        }
        __syncthreads();
    }
    #pragma unroll
    for (int u = 0; u < 4; u++) {
        float bt = top_b[p0 + u], bc = cen_b[p0 + u];
        float4 o;
        o.x = at[u][0] + bt; o.y = at[u][1] + bt; o.z = at[u][2] + bt; o.w = at[u][3] + bt;
        *(float4*)(g_top + b * (PP * HW) + (p0 + u) * HW + n0 + j0) = o;
        #pragma unroll
        for (int v = 0; v < 4; v++)
            g_centerT[b * (HW * PP) + (n0 + j0 + v) * PP + p0 + u] = ac[u][v] + bc;
    }
}

// ---------------- K3/K7: 3x3 SelfONN conv via mma.sync (shifted-view GEMM) ----------
// Block: 128 px (2 image rows) x 64 oc, 256 threads (8 warps, warp tile 32px x 32oc).
// 12 chunks of 16 input power-channels; 9 taps = 9 shifted A-views via ldmatrix
// per-lane pointers. bf16-split 3-term (Xh*Wh + Xl*Wh + Xh*Wl), fp32 accum.
#define CV_A_HI 0                        // [4 r][68 c][16 ic] bf16, 48B px-stride
#define CV_A_LO (CV_A_HI + 4*68*48)      // 13056 B each
#define CV_W_HI (CV_A_LO + 13056)        // [9 tap][16 ic][72 oc] bf16, 144B ic-stride
#define CV_W_LO (CV_W_HI + 20736)
#define SMEM_CV (CV_W_LO + 20736)        // 67584 B

template <bool FINAL>
__global__ void __launch_bounds__(256, 2)
k_conv3(const float* __restrict__ w, const float* __restrict__ bias,
        const float* __restrict__ x, float* __restrict__ out) {
    extern __shared__ char smem[];
    unsigned sb;
    asm("{ .reg .u64 t; cvta.to.shared.u64 t, %1; cvt.u32.u64 %0, t; }"
        : "=r"(sb) : "l"(smem));
    int b  = blockIdx.y;
    int h0 = blockIdx.x * 2;
    int tid = threadIdx.x;
    int wid = tid >> 5, lid = tid & 31;
    int wpx = (wid >> 1) * 32;
    int woc = (wid & 1) * 32;

    float acc[2][4][4];
    #pragma unroll
    for (int mt = 0; mt < 2; mt++)
        #pragma unroll
        for (int nt = 0; nt < 4; nt++)
            #pragma unroll
            for (int e = 0; e < 4; e++) acc[mt][nt][e] = 0.0f;

    // per-lane A-fragment base pointers (pixel row of this lane, k-half offset)
    unsigned abase[2];
    #pragma unroll
    for (int mt = 0; mt < 2; mt++) {
        int px = wpx + mt * 16 + (lid & 15);
        int r = px >> 6, col = px & 63;
        abase[mt] = sb + CV_A_HI + (unsigned)((r * 68 + col) * 48) + ((lid >> 4) * 16);
    }
    int bkrow = lid & 15;

    for (int cc = 0; cc < 12; cc++) {
        int qi = cc >> 2;                    // power index, constant per 16-ch chunk
        int cb = (cc * 16) & 63;
        // ---- stage input tile: 272 positions x 8 ic-pairs -> bf16 hi/lo ----
        #pragma unroll
        for (int it = 0; it < 9; it++) {
            int idx = tid + it * 256;
            if (idx < 2176) {
                int icp = idx & 7;
                int pos = idx >> 3;          // 0..271 = rr*68 + colc
                int rr  = pos / 68;
                int colc = pos - rr * 68;
                int gh = h0 - 1 + rr, gw = colc - 1;
                float y0 = 0.0f, y1 = 0.0f;
                if ((unsigned)gh < HH && (unsigned)gw < WW) {
                    int g0 = ((b * CC + cb + icp * 2) << 12) + (gh << 6) + gw;
                    y0 = x[g0]; y1 = x[g0 + 4096];
                    if (FINAL) {
                        y0 += g_spv[0][g0] + g_spv[1][g0];
                        y1 += g_spv[0][g0 + 4096] + g_spv[1][g0 + 4096];
                    }
                    float p0 = y0, p1 = y1;
                    if (qi >= 1) { p0 *= y0; p1 *= y1; }
                    if (qi == 2) { p0 *= y0; p1 *= y1; }
                    y0 = p0; y1 = p1;
                }
                __nv_bfloat162 h = __floats2bfloat162_rn(y0, y1);
                float2 f = __bfloat1622float2(h);
                __nv_bfloat162 l = __floats2bfloat162_rn(y0 - f.x, y1 - f.y);
                unsigned off = pos * 48 + icp * 4;
                *(unsigned*)(smem + CV_A_HI + off) = *(unsigned*)&h;
                *(unsigned*)(smem + CV_A_LO + off) = *(unsigned*)&l;
            }
        }
        // ---- stage weights: idx = oc*144 + ic*9 + tap (coalesced per-oc reads) ----
        #pragma unroll
        for (int it = 0; it < 36; it++) {
            int idx = tid + it * 256;            // 9216 exactly
            int oc  = idx / 144;
            int rem = idx - oc * 144;
            int ic  = rem / 9;
            int tap = rem - ic * 9;
            float wv = w[(oc * KCH + cc * 16 + ic) * 9 + tap];
            __nv_bfloat16 hh = __float2bfloat16(wv);
            __nv_bfloat16 ll = __float2bfloat16(wv - __bfloat162float(hh));
            unsigned off = tap * 2304 + ic * 144 + oc * 2;
            *(__nv_bfloat16*)(smem + CV_W_HI + off) = hh;
            *(__nv_bfloat16*)(smem + CV_W_LO + off) = ll;
        }
        __syncthreads();
        // ---- 9 taps: shifted A views + per-tap weights ----
        #pragma unroll
        for (int dy = 0; dy < 3; dy++)
            #pragma unroll
            for (int dx = 0; dx < 3; dx++) {
                unsigned ash = (unsigned)((dy * 68 + dx) * 48);
                unsigned ah[2][4], al[2][4];
                #pragma unroll
                for (int mt = 0; mt < 2; mt++) {
                    ldsm_x4(ah[mt], abase[mt] + ash);
                    ldsm_x4(al[mt], abase[mt] + ash + (CV_A_LO - CV_A_HI));
                }
                unsigned tw = sb + CV_W_HI + (dy * 3 + dx) * 2304 + bkrow * 144 + woc * 2;
                unsigned bh[4][2], bl[4][2];
                #pragma unroll
                for (int nt = 0; nt < 4; nt++) {
                    ldsm_x2t(bh[nt], tw + nt * 16);
                    ldsm_x2t(bl[nt], tw + nt * 16 + (CV_W_LO - CV_W_HI));
                }
                #pragma unroll
                for (int mt = 0; mt < 2; mt++)
                    #pragma unroll
                    for (int nt = 0; nt < 4; nt++) {
                        mma_bf16(acc[mt][nt], ah[mt], bh[nt]);
                        mma_bf16(acc[mt][nt], al[mt], bh[nt]);
                        mma_bf16(acc[mt][nt], ah[mt], bl[nt]);
                    }
            }
        __syncthreads();
    }

    // ---- epilogue: bias, store ----
    #pragma unroll
    for (int mt = 0; mt < 2; mt++)
        #pragma unroll
        for (int nt = 0; nt < 4; nt++) {
            int oc  = woc + nt * 8 + (lid & 3) * 2;
            int px0 = wpx + mt * 16 + (lid >> 2);
            int px1 = px0 + 8;
            float b0 = bias[oc], b1 = bias[oc + 1];
            float e0 = acc[mt][nt][0] + b0, e1 = acc[mt][nt][1] + b1;
            float e2 = acc[mt][nt][2] + b0, e3 = acc[mt][nt][3] + b1;
            if (FINAL) {
                int base = (b * CC + oc) << 12;
                int pxg0 = (h0 << 6) + px0;
                int pxg1 = (h0 << 6) + px1;
                out[base + pxg0]          = e0;
                out[base + 4096 + pxg0]   = e1;
                out[base + pxg1]          = e2;
                out[base + 4096 + pxg1]   = e3;
            } else {
                float* O = g_bottomT + b * (HW * CC);
                *(float2*)(O + ((h0 << 6) + px0) * CC + oc) = make_float2(e0, e1);
                *(float2*)(O + ((h0 << 6) + px1) * CC + oc) = make_float2(e2, e3);
            }
        }
}

// ---------------- K4: QK via mma.sync bf16-split + tile-local softmax ----------------
// Epilogue stores exp(sp - tmax) as ONE bf16 plane; tile sums use the ROUNDED values.
#define OFF_A_HI  128                       // [128 n][72 k] bf16 (144B rows)
#define OFF_A_LO  (OFF_A_HI + 128*144)
#define OFF_B_HI  (OFF_A_LO + 128*144)      // [64 k][136 m] bf16 (272B rows)
#define OFF_B_LO  (OFF_B_HI + 64*272)
#define SMEM_QK   (OFF_B_LO + 64*272)       // 71808 B

__global__ void __launch_bounds__(256, 2)
k_qk_mma() {
    extern __shared__ char smem[];
    unsigned sb;
    asm("{ .reg .u64 t; cvta.to.shared.u64 t, %1; cvt.u32.u64 %0, t; }"
        : "=r"(sb) : "l"(smem));
    int b  = blockIdx.z;
    int m0 = blockIdx.x * 128;
    int n0 = blockIdx.y * 128;
    int tid = threadIdx.x;
    int wid = tid >> 5, lid = tid & 31;
    float* s_red = (float*)smem;

    // ---- stage A (centerT rows, hi/lo) ----
    const float* Ag = g_centerT + (size_t)b * (HW * PP);
    #pragma unroll 2
    for (int it = 0; it < 8; it++) {
        int idx = tid + it * 256;          // 2048: n(128) x kf4(16)
        int n = idx >> 4, kf4 = idx & 15;
        float4 v = *(const float4*)(Ag + (n0 + n) * PP + 4 * kf4);
        unsigned hi[2], lo[2];
        cvt4(v, hi, lo);
        *(uint2*)(smem + OFF_A_HI + n * 144 + 8 * kf4) = make_uint2(hi[0], hi[1]);
        *(uint2*)(smem + OFF_A_LO + n * 144 + 8 * kf4) = make_uint2(lo[0], lo[1]);
    }
    // ---- stage B (top rows [k][m], hi/lo) ----
    const float* Bg = g_top + (size_t)b * (PP * HW) + m0;
    #pragma unroll 2
    for (int it = 0; it < 8; it++) {
        int idx = tid + it * 256;          // 2048: k(64) x mf4(32)
        int k = idx >> 5, mf4 = idx & 31;
        float4 v = *(const float4*)(Bg + k * HW + 4 * mf4);
        unsigned hi[2], lo[2];
        cvt4(v, hi, lo);
        *(uint2*)(smem + OFF_B_HI + k * 272 + 8 * mf4) = make_uint2(hi[0], hi[1]);
        *(uint2*)(smem + OFF_B_LO + k * 272 + 8 * mf4) = make_uint2(lo[0], lo[1]);
    }
    __syncthreads();

    // ---- warp tiling: warp_n = wid>>1 (4 x 32 rows), warp_m = wid&1 (2 x 64 cols) ----
    int wn = (wid >> 1) * 32;
    int wm = (wid & 1) * 64;
    float acc[2][8][4];
    #pragma unroll
    for (int mt = 0; mt < 2; mt++)
        #pragma unroll
        for (int nt = 0; nt < 8; nt++)
            #pragma unroll
            for (int e = 0; e < 4; e++) acc[mt][nt][e] = 0.0f;

    int arow = wn + (lid & 15);
    int acolB = (lid >> 4) * 8;
    int bkrow = (lid & 15);

    #pragma unroll
    for (int ks = 0; ks < 4; ks++) {
        int k0 = ks * 16;
        unsigned ah[2][4], al[2][4];
        #pragma unroll
        for (int mt = 0; mt < 2; mt++) {
            unsigned aaddr = sb + OFF_A_HI + (arow + mt * 16) * 144 + (k0 + acolB) * 2;
            ldsm_x4(ah[mt], aaddr);
            ldsm_x4(al[mt], aaddr + (OFF_A_LO - OFF_A_HI));
        }
        unsigned bf[8][2];
        #pragma unroll
        for (int nt = 0; nt < 8; nt++)
            ldsm_x2t(bf[nt], sb + OFF_B_HI + (k0 + bkrow) * 272 + (wm + nt * 8) * 2);
        #pragma unroll
        for (int mt = 0; mt < 2; mt++)
            #pragma unroll
            for (int nt = 0; nt < 8; nt++) {
                mma_bf16(acc[mt][nt], ah[mt], bf[nt]);
                mma_bf16(acc[mt][nt], al[mt], bf[nt]);
            }
        #pragma unroll
        for (int nt = 0; nt < 8; nt++)
            ldsm_x2t(bf[nt], sb + OFF_B_LO + (k0 + bkrow) * 272 + (wm + nt * 8) * 2);
        #pragma unroll
        for (int mt = 0; mt < 2; mt++)
            #pragma unroll
            for (int nt = 0; nt < 8; nt++)
                mma_bf16(acc[mt][nt], ah[mt], bf[nt]);
    }

    // ---- tile max (block-wide) ----
    float mx = -INFINITY;
    #pragma unroll
    for (int mt = 0; mt < 2; mt++)
        #pragma unroll
        for (int nt = 0; nt < 8; nt++)
            #pragma unroll
            for (int e = 0; e < 4; e++)
                mx = fmaxf(mx, acc[mt][nt][e]);
    #pragma unroll
    for (int off = 16; off > 0; off >>= 1)
        mx = fmaxf(mx, __shfl_xor_sync(0xffffffffu, mx, off));
    if (lid == 0) s_red[wid] = mx;
    __syncthreads();
    float tmax = s_red[0];
    #pragma unroll
    for (int i = 1; i < 8; i++) tmax = fmaxf(tmax, s_red[i]);

    // ---- packed exp(sp - tmax) -> bf16, sum the ROUNDED values, store ----
    const u64 L2E   = dup2(1.4426950408889634f);
    const u64 TOFF  = dup2(-tmax * 1.4426950408889634f);
    const u64 MAGIC = dup2(12582912.0f);
    const u64 NMAG  = dup2(-12582912.0f);
    const u64 NEG1  = dup2(-1.0f);
    const u64 C6 = dup2(1.5403530e-4f), C5 = dup2(1.3333558e-3f);
    const u64 C4 = dup2(9.6181291e-3f), C3 = dup2(5.5504109e-2f);
    const u64 C2 = dup2(2.4022651e-1f), C1 = dup2(6.9314718e-1f);
    const u64 ONE = dup2(1.0f);
    float ssum = 0.0f;
    unsigned* Ho = g_sph + ((size_t)b << 23);
    int rbase = n0 + wn + (lid >> 2);
    int cbase = m0 + wm + (lid & 3) * 2;
    #pragma unroll
    for (int mt = 0; mt < 2; mt++)
        #pragma unroll
        for (int nt = 0; nt < 8; nt++) {
            u64 e01 = fexp2pair(pk2(acc[mt][nt][0], acc[mt][nt][1]),
                                L2E, TOFF, MAGIC, NMAG, NEG1,
                                C6, C5, C4, C3, C2, C1, ONE);
            u64 e23 = fexp2pair(pk2(acc[mt][nt][2], acc[mt][nt][3]),
                                L2E, TOFF, MAGIC, NMAG, NEG1,
                                C6, C5, C4, C3, C2, C1, ONE);
            float e0, e1, e2, e3;
            up2(e01, e0, e1); up2(e23, e2, e3);
            __nv_bfloat162 h01 = __floats2bfloat162_rn(e0, e1);
            __nv_bfloat162 h23 = __floats2bfloat162_rn(e2, e3);
            float2 f0 = __bfloat1622float2(h01);
            float2 f1 = __bfloat1622float2(h23);
            ssum += (f0.x + f0.y) + (f1.x + f1.y);
            int cc = cbase + nt * 8;
            Ho[((size_t)(rbase + mt * 16) * HW + cc) >> 1] = *(unsigned*)&h01;
            Ho[((size_t)(rbase + mt * 16 + 8) * HW + cc) >> 1] = *(unsigned*)&h23;
        }
    #pragma unroll
    for (int off = 16; off > 0; off >>= 1)
        ssum += __shfl_xor_sync(0xffffffffu, ssum, off);
    __syncthreads();
    if (lid == 0) s_red[wid] = ssum;
    __syncthreads();
    if (tid == 0) {
        float t = 0.0f;
        #pragma unroll
        for (int i = 0; i < 8; i++) t += s_red[i];
        int tile = blockIdx.y * 32 + blockIdx.x;
        g_tmax[b][tile] = tmax;
        g_tsum[b][tile] = t;
    }
}

// ---------------- K5: combine per-tile (max,sum) -> global (max,sum) ----------------
__global__ void k_combine() {
    int b = blockIdx.x;
    int tid = threadIdx.x;               // 1024 threads, one per tile
    __shared__ float s_red[32];
    float v = g_tmax[b][tid];
    float mx = v;
    #pragma unroll
    for (int off = 16; off > 0; off >>= 1)
        mx = fmaxf(mx, __shfl_xor_sync(0xffffffffu, mx, off));
    if ((tid & 31) == 0) s_red[tid >> 5] = mx;
    __syncthreads();
    if (tid < 32) {
        float m2 = s_red[tid];
        #pragma unroll
        for (int off = 16; off > 0; off >>= 1)
            m2 = fmaxf(m2, __shfl_xor_sync(0xffffffffu, m2, off));
        if (tid == 0) s_red[0] = m2;
    }
    __syncthreads();
    float gmax = s_red[0];
    __syncthreads();
    float part = g_tsum[b][tid] * fexp(v - gmax);
    #pragma unroll
    for (int off = 16; off > 0; off >>= 1)
        part += __shfl_xor_sync(0xffffffffu, part, off);
    __shared__ float s_sum[32];
    if ((tid & 31) == 0) s_sum[tid >> 5] = part;
    __syncthreads();
    if (tid < 32) {
        float t = s_sum[tid];
        #pragma unroll
        for (int off = 16; off > 0; off >>= 1)
            t += __shfl_xor_sync(0xffffffffu, t, off);
        if (tid == 0) { g_max[b] = gmax; g_sum[b] = t; }
    }
}

// ---------------- K6: spv = E @ bottomT via mma.sync (E bf16, B split), split-K 2 ----
#define AV_A_HI 0                           // [128 n][72 k] bf16 (144B rows)
#define AV_B_HI (AV_A_HI + 128*144)         // [64 k][72 c] bf16 (144B rows)
#define AV_B_LO (AV_B_HI + 64*144)
#define SMEM_AV (AV_B_LO + 64*144)          // 36864 B

__global__ void __launch_bounds__(256, 3)
k_av_mma() {
    extern __shared__ char smem[];
    unsigned sb;
    asm("{ .reg .u64 t; cvta.to.shared.u64 t, %1; cvt.u32.u64 %0, t; }"
        : "=r"(sb) : "l"(smem));
    int b  = blockIdx.z;
    int ks = blockIdx.y;
    int n0 = blockIdx.x * 128;
    int tid = threadIdx.x;
    int wid = tid >> 5, lid = tid & 31;
    int wn = (wid >> 1) * 32;       // warp rows
    int wc = (wid & 1) * 32;        // warp cols
    const unsigned* Hp = g_sph + ((size_t)b << 23);
    const float* BT = g_bottomT + b * (HW * CC);
    float gmax = g_max[b];
    int trow = (n0 >> 7) * 32;

    float acc[2][4][4];
    #pragma unroll
    for (int mt = 0; mt < 2; mt++)
        #pragma unroll
        for (int nt = 0; nt < 4; nt++)
            #pragma unroll
            for (int e = 0; e < 4; e++) acc[mt][nt][e] = 0.0f;

    int arow = wn + (lid & 15);
    int acolB = (lid >> 4) * 8;
    int bkrow = (lid & 15);

    for (int kc = 0; kc < 2048; kc += 64) {
        int kbase = ks * 2048 + kc;
        // ---- stage A: bf16 E plane straight from gmem ----
        #pragma unroll
        for (int it = 0; it < 4; it++) {
            int idx = tid + it * 256;              // 1024: row(128) x j(8)
            int row = idx >> 3, j = idx & 7;
            size_t off = (size_t)(n0 + row) * (HW / 2) + (kbase >> 1) + j * 4;
            *(uint4*)(smem + AV_A_HI + row * 144 + j * 16) = *(const uint4*)(Hp + off);
        }
        // ---- stage B: bottomT scaled by s(k-strip), bf16-split in regs ----
        float s = fexp(g_tmax[b][trow + (kbase >> 7)] - gmax);
        #pragma unroll
        for (int it = 0; it < 4; it++) {
            int idx = tid + it * 256;              // 1024: k(64) x j(16)
            int k = idx >> 4, j = idx & 15;
            float4 v = *(const float4*)(BT + (kbase + k) * CC + 4 * j);
            v.x *= s; v.y *= s; v.z *= s; v.w *= s;
            unsigned hi[2], lo[2];
            cvt4(v, hi, lo);
            *(uint2*)(smem + AV_B_HI + k * 144 + j * 8) = make_uint2(hi[0], hi[1]);
            *(uint2*)(smem + AV_B_LO + k * 144 + j * 8) = make_uint2(lo[0], lo[1]);
        }
        __syncthreads();
        // ---- 4 k-steps of 16 ----
        #pragma unroll
        for (int k8 = 0; k8 < 4; k8++) {
            int k0 = k8 * 16;
            unsigned ah[2][4];
            #pragma unroll
            for (int mt = 0; mt < 2; mt++)
                ldsm_x4(ah[mt], sb + AV_A_HI + (arow + mt * 16) * 144 + (k0 + acolB) * 2);
            unsigned bh[4][2], bl[4][2];
            #pragma unroll
            for (int nt = 0; nt < 4; nt++) {
                unsigned baddr = sb + AV_B_HI + (k0 + bkrow) * 144 + (wc + nt * 8) * 2;
                ldsm_x2t(bh[nt], baddr);
                ldsm_x2t(bl[nt], baddr + (AV_B_LO - AV_B_HI));
            }
            #pragma unroll
            for (int mt = 0; mt < 2; mt++)
                #pragma unroll
                for (int nt = 0; nt < 4; nt++) {
                    mma_bf16(acc[mt][nt], ah[mt], bh[nt]);
                    mma_bf16(acc[mt][nt], ah[mt], bl[nt]);
                }
        }
        __syncthreads();
    }

    // ---- epilogue: / gsum, write split-K partial ----
    float inv = 1.0f / g_sum[b];
    float* O = g_spv[ks] + b * (HW * CC);
    int rbase = n0 + wn + (lid >> 2);
    int cbase = wc + (lid & 3) * 2;
    #pragma unroll
    for (int mt = 0; mt < 2; mt++)
        #pragma unroll
        for (int nt = 0; nt < 4; nt++) {
            int cc = cbase + nt * 8;
            *(float2*)(O + (rbase + mt * 16) * CC + cc) =
                make_float2(acc[mt][nt][0] * inv, acc[mt][nt][1] * inv);
            *(float2*)(O + (rbase + mt * 16 + 8) * CC + cc) =
                make_float2(acc[mt][nt][2] * inv, acc[mt][nt][3] * inv);
        }
}

// ---------------- launch ----------------
extern "C" void kernel_launch(void* const* d_in, const int* in_sizes, int n_in,
                              void* d_out, int out_size) {
    (void)in_sizes; (void)n_in; (void)out_size;
    const float* x     = (const float*)d_in[0];
    const float* top_w = (const float*)d_in[1];
    const float* top_b = (const float*)d_in[2];
    const float* cen_w = (const float*)d_in[3];
    const float* cen_b = (const float*)d_in[4];
    const float* bot_w = (const float*)d_in[5];
    const float* bot_b = (const float*)d_in[6];
    const float* out_w = (const float*)d_in[7];
    const float* out_b = (const float*)d_in[8];
    float* out = (float*)d_out;

    cudaFuncSetAttribute(k_qk_mma, cudaFuncAttributeMaxDynamicSharedMemorySize, SMEM_QK);
    cudaFuncSetAttribute(k_av_mma, cudaFuncAttributeMaxDynamicSharedMemorySize, SMEM_AV);
    cudaFuncSetAttribute(k_conv3<false>, cudaFuncAttributeMaxDynamicSharedMemorySize, SMEM_CV);
    cudaFuncSetAttribute(k_conv3<true>,  cudaFuncAttributeMaxDynamicSharedMemorySize, SMEM_CV);

    k_proj<<<dim3(64, 4), 256>>>(x, top_w, top_b, cen_w, cen_b);
    k_conv3<false><<<dim3(32, 4), 256, SMEM_CV>>>(bot_w, bot_b, x, nullptr);
    k_qk_mma<<<dim3(32, 32, 4), 256, SMEM_QK>>>();
    k_combine<<<4, 1024>>>();
    k_av_mma<<<dim3(32, 2, 4), 256, SMEM_AV>>>();
    k_conv3<true><<<dim3(32, 4), 256, SMEM_CV>>>(out_w, out_b, x, out);
}

// round 17
// speedup vs baseline: 1.9924x; 1.4149x over previous
#include <cuda_runtime.h>
#include <cuda_bf16.h>
#include <math.h>

// ---------------- problem constants ----------------
#define BB  4
#define CC  64
#define HH  64
#define WW  64
#define HW  4096      // 64*64
#define KCH 192       // C*Q
#define PP  64
#define NTILE 1024    // 32x32 sp tiles per batch
#define WCV_N (12*9*16*72)   // pre-split conv weights per set per plane

typedef unsigned long long u64;

// ---------------- scratch (no allocations allowed) ----------------
__device__ __align__(128) float g_top[BB * PP * HW];        // (b,p,n)
__device__ __align__(128) float g_centerT[BB * HW * PP];    // (b,n,p)
__device__ __align__(128) float g_bottomT[BB * HW * CC];    // (b,m,c)
__device__ __align__(128) unsigned g_sph[(size_t)BB * HW * HW / 2];  // 134MB E plane
__device__ __align__(128) float g_spv[2][BB * HW * CC];     // split-K partials
__device__ __align__(128) float g_tmax[BB][NTILE];
__device__ __align__(128) float g_tsum[BB][NTILE];
__device__ float g_max[BB];
__device__ float g_sum[BB];
__device__ __align__(128) __nv_bfloat16 g_wcv[2][2][WCV_N]; // [set][hi/lo] conv weights

// ---------------- packed f32x2 helpers ----------------
__device__ __forceinline__ u64 pk2(float lo, float hi) {
    u64 r; asm("mov.b64 %0,{%1,%2};" : "=l"(r) : "f"(lo), "f"(hi)); return r;
}
__device__ __forceinline__ u64 dup2(float a) { return pk2(a, a); }
__device__ __forceinline__ void up2(u64 v, float& lo, float& hi) {
    asm("mov.b64 {%0,%1},%2;" : "=f"(lo), "=f"(hi) : "l"(v));
}
__device__ __forceinline__ u64 fma2(u64 a, u64 b, u64 c) {
    u64 d; asm("fma.rn.f32x2 %0,%1,%2,%3;" : "=l"(d) : "l"(a), "l"(b), "l"(c)); return d;
}
__device__ __forceinline__ u64 mul2(u64 a, u64 b) {
    u64 d; asm("mul.rn.f32x2 %0,%1,%2;" : "=l"(d) : "l"(a), "l"(b)); return d;
}
__device__ __forceinline__ u64 add2(u64 a, u64 b) {
    u64 d; asm("add.rn.f32x2 %0,%1,%2;" : "=l"(d) : "l"(a), "l"(b)); return d;
}

// FMA-pipe exp (scalar), x <= 0 expected, clamped at -80.
__device__ __forceinline__ float fexp(float x) {
    x = fmaxf(x, -80.0f);
    float t = x * 1.4426950408889634f;
    float n = rintf(t);
    float f = t - n;
    float p = 1.5403530e-4f;
    p = fmaf(p, f, 1.3333558e-3f);
    p = fmaf(p, f, 9.6181291e-3f);
    p = fmaf(p, f, 5.5504109e-2f);
    p = fmaf(p, f, 2.4022651e-1f);
    p = fmaf(p, f, 6.9314718e-1f);
    p = fmaf(p, f, 1.0f);
    int e = (int)n;
    return p * __int_as_float((e + 127) << 23);
}

// packed exp2-based exp(x - off): caller folds offset into TOFF
__device__ __forceinline__ u64 fexp2pair(u64 x2, u64 L2E, u64 TOFF,
                                         u64 MAGIC, u64 NMAG, u64 NEG1,
                                         u64 C6, u64 C5, u64 C4, u64 C3,
                                         u64 C2, u64 C1, u64 ONE) {
    u64 t  = fma2(x2, L2E, TOFF);
    u64 z  = add2(t, MAGIC);
    u64 nf = add2(z, NMAG);
    u64 f  = fma2(nf, NEG1, t);
    u64 p  = fma2(C6, f, C5);
    p = fma2(p, f, C4); p = fma2(p, f, C3);
    p = fma2(p, f, C2); p = fma2(p, f, C1);
    p = fma2(p, f, ONE);
    unsigned zl, zh;
    asm("mov.b64 {%0,%1},%2;" : "=r"(zl), "=r"(zh) : "l"(z));
    int el = max((int)zl - 0x4B400000, -126) + 127;
    int eh = max((int)zh - 0x4B400000, -126) + 127;
    u64 s = pk2(__int_as_float(el << 23), __int_as_float(eh << 23));
    return mul2(p, s);
}

// ---------------- mma.sync / ldmatrix helpers (baseline PTX) ----------------
__device__ __forceinline__ void ldsm_x4(unsigned* r, unsigned a) {
    asm volatile("ldmatrix.sync.aligned.m8n8.x4.shared.b16 {%0,%1,%2,%3}, [%4];"
        : "=r"(r[0]), "=r"(r[1]), "=r"(r[2]), "=r"(r[3]) : "r"(a));
}
__device__ __forceinline__ void ldsm_x2t(unsigned* r, unsigned a) {
    asm volatile("ldmatrix.sync.aligned.m8n8.x2.trans.shared.b16 {%0,%1}, [%2];"
        : "=r"(r[0]), "=r"(r[1]) : "r"(a));
}
__device__ __forceinline__ void mma_bf16(float* d, const unsigned* a, const unsigned* b) {
    asm volatile("mma.sync.aligned.m16n8k16.row.col.f32.bf16.bf16.f32 "
        "{%0,%1,%2,%3}, {%4,%5,%6,%7}, {%8,%9}, {%0,%1,%2,%3};"
        : "+f"(d[0]), "+f"(d[1]), "+f"(d[2]), "+f"(d[3])
        : "r"(a[0]), "r"(a[1]), "r"(a[2]), "r"(a[3]), "r"(b[0]), "r"(b[1]));
}

// split one float4 into hi/lo bf16x2 pairs
__device__ __forceinline__ void cvt4(float4 v, unsigned* hi, unsigned* lo) {
    float a[4] = {v.x, v.y, v.z, v.w};
    #pragma unroll
    for (int p = 0; p < 2; p++) {
        __nv_bfloat162 h = __floats2bfloat162_rn(a[2*p], a[2*p+1]);
        float2 f = __bfloat1622float2(h);
        __nv_bfloat162 l = __floats2bfloat162_rn(a[2*p] - f.x, a[2*p+1] - f.y);
        hi[p] = *(unsigned*)&h;
        lo[p] = *(unsigned*)&l;
    }
}

// ---------------- K0: pre-split conv weights into bf16 hi/lo planes ----------------
// Layout per set: [chunk][tap][ic][oc72] contiguous bf16, oc 64..71 zero-padded.
__global__ void k_wprep(const float* __restrict__ bw, const float* __restrict__ ow) {
    int idx = blockIdx.x * 256 + threadIdx.x;
    if (idx >= WCV_N) return;
    int oc  = idx % 72;
    int rem = idx / 72;          // (chunk*9 + tap)*16 + ic
    int ic  = rem % 16;
    int tt  = rem / 16;
    int tap = tt % 9;
    int chunk = tt / 9;
    float w0 = 0.0f, w1 = 0.0f;
    if (oc < 64) {
        int widx = (oc * KCH + chunk * 16 + ic) * 9 + tap;
        w0 = bw[widx];
        w1 = ow[widx];
    }
    __nv_bfloat16 h0 = __float2bfloat16(w0);
    __nv_bfloat16 h1 = __float2bfloat16(w1);
    g_wcv[0][0][idx] = h0;
    g_wcv[0][1][idx] = __float2bfloat16(w0 - __bfloat162float(h0));
    g_wcv[1][0][idx] = h1;
    g_wcv[1][1][idx] = __float2bfloat16(w1 - __bfloat162float(h1));
}

// ---------------- K2: 1x1 SelfONN convs (top & center), powers inline ----------------
__global__ void k_proj(const float* __restrict__ x,
                       const float* __restrict__ top_w, const float* __restrict__ top_b,
                       const float* __restrict__ cen_w, const float* __restrict__ cen_b) {
    __shared__ __align__(16) float As_t[32 * 68];
    __shared__ __align__(16) float As_c[32 * 68];
    __shared__ __align__(16) float Bs[32 * 64];
    int b  = blockIdx.y;
    int n0 = blockIdx.x * 64;
    int tid = threadIdx.x;
    int p0 = (tid >> 4) * 4;
    int j0 = (tid & 15) * 4;
    float at[4][4] = {}, ac[4][4] = {};

    for (int kc = 0; kc < KCH; kc += 32) {
        int q = kc >> 6;
        #pragma unroll
        for (int it = 0; it < 2; it++) {
            int f4 = tid + it * 256;
            int p = f4 >> 3, k4 = f4 & 7;
            float4 vt = *(const float4*)(top_w + p * KCH + kc + 4 * k4);
            float4 vc = *(const float4*)(cen_w + p * KCH + kc + 4 * k4);
            As_t[(4*k4+0)*68 + p] = vt.x; As_t[(4*k4+1)*68 + p] = vt.y;
            As_t[(4*k4+2)*68 + p] = vt.z; As_t[(4*k4+3)*68 + p] = vt.w;
            As_c[(4*k4+0)*68 + p] = vc.x; As_c[(4*k4+1)*68 + p] = vc.y;
            As_c[(4*k4+2)*68 + p] = vc.z; As_c[(4*k4+3)*68 + p] = vc.w;
        }
        #pragma unroll
        for (int it = 0; it < 2; it++) {
            int f4 = tid + it * 256;
            int k = f4 >> 4, j4 = f4 & 15;
            int c = (kc + k) & 63;
            float4 v = *(const float4*)(x + ((b * CC + c) << 12) + n0 + 4 * j4);
            if (q >= 1) { v.x *= v.x ; v.y *= v.y ; v.z *= v.z ; v.w *= v.w; }
            if (q == 2) {
                float4 v1 = *(const float4*)(x + ((b * CC + c) << 12) + n0 + 4 * j4);
                v.x *= v1.x; v.y *= v1.y; v.z *= v1.z; v.w *= v1.w;
            }
            *(float4*)(Bs + k * 64 + 4 * j4) = v;
        }
        __syncthreads();
        #pragma unroll 8
        for (int k = 0; k < 32; k++) {
            float a1[4]; *(float4*)a1 = *(float4*)(As_t + k * 68 + p0);
            float a2[4]; *(float4*)a2 = *(float4*)(As_c + k * 68 + p0);
            float bv[4]; *(float4*)bv = *(float4*)(Bs  + k * 64 + j0);
            #pragma unroll
            for (int u = 0; u < 4; u++)
                #pragma unroll
                for (int v = 0; v < 4; v++) {
                    at[u][v] = fmaf(a1[u], bv[v], at[u][v]);
                    ac[u][v] = fmaf(a2[u], bv[v], ac[u][v]);
                }
        }
        __syncthreads();
    }
    #pragma unroll
    for (int u = 0; u < 4; u++) {
        float bt = top_b[p0 + u], bc = cen_b[p0 + u];
        float4 o;
        o.x = at[u][0] + bt; o.y = at[u][1] + bt; o.z = at[u][2] + bt; o.w = at[u][3] + bt;
        *(float4*)(g_top + b * (PP * HW) + (p0 + u) * HW + n0 + j0) = o;
        #pragma unroll
        for (int v = 0; v < 4; v++)
            g_centerT[b * (HW * PP) + (n0 + j0 + v) * PP + p0 + u] = ac[u][v] + bc;
    }
}

// ---------------- K3/K7: 3x3 SelfONN conv via mma.sync (shifted-view GEMM) ----------
#define CV_A_HI 0                        // [4 r][68 c][16 ic] bf16, 48B px-stride
#define CV_A_LO (CV_A_HI + 4*68*48)      // 13056 B each
#define CV_W_HI (CV_A_LO + 13056)        // [9 tap][16 ic][72 oc] bf16, 144B ic-stride
#define CV_W_LO (CV_W_HI + 20736)
#define SMEM_CV (CV_W_LO + 20736)        // 67584 B

template <bool FINAL>
__global__ void __launch_bounds__(256, 2)
k_conv3(const float* __restrict__ bias,
        const float* __restrict__ x, float* __restrict__ out) {
    extern __shared__ char smem[];
    unsigned sb;
    asm("{ .reg .u64 t; cvta.to.shared.u64 t, %1; cvt.u32.u64 %0, t; }"
        : "=r"(sb) : "l"(smem));
    int b  = blockIdx.y;
    int h0 = blockIdx.x * 2;
    int tid = threadIdx.x;
    int wid = tid >> 5, lid = tid & 31;
    int wpx = (wid >> 1) * 32;
    int woc = (wid & 1) * 32;

    float acc[2][4][4];
    #pragma unroll
    for (int mt = 0; mt < 2; mt++)
        #pragma unroll
        for (int nt = 0; nt < 4; nt++)
            #pragma unroll
            for (int e = 0; e < 4; e++) acc[mt][nt][e] = 0.0f;

    unsigned abase[2];
    #pragma unroll
    for (int mt = 0; mt < 2; mt++) {
        int px = wpx + mt * 16 + (lid & 15);
        int r = px >> 6, col = px & 63;
        abase[mt] = sb + CV_A_HI + (unsigned)((r * 68 + col) * 48) + ((lid >> 4) * 16);
    }
    int bkrow = lid & 15;
    const uint4* Wh0 = (const uint4*)g_wcv[FINAL ? 1 : 0][0];
    const uint4* Wl0 = (const uint4*)g_wcv[FINAL ? 1 : 0][1];

    for (int cc = 0; cc < 12; cc++) {
        int qi = cc >> 2;
        int cb = (cc * 16) & 63;
        // ---- stage input tile (coalesced: lanes = consecutive pixels) ----
        #pragma unroll
        for (int it = 0; it < 9; it++) {
            int idx = tid + it * 256;
            if (idx < 2176) {
                int icp = idx / 272;
                int pos = idx - icp * 272;   // rr*68 + colc, lanes consecutive in colc
                int rr  = pos / 68;
                int colc = pos - rr * 68;
                int gh = h0 - 1 + rr, gw = colc - 1;
                float y0 = 0.0f, y1 = 0.0f;
                if ((unsigned)gh < HH && (unsigned)gw < WW) {
                    int g0 = ((b * CC + cb + icp * 2) << 12) + (gh << 6) + gw;
                    y0 = x[g0]; y1 = x[g0 + 4096];
                    if (FINAL) {
                        y0 += g_spv[0][g0] + g_spv[1][g0];
                        y1 += g_spv[0][g0 + 4096] + g_spv[1][g0 + 4096];
                    }
                    float p0 = y0, p1 = y1;
                    if (qi >= 1) { p0 *= y0; p1 *= y1; }
                    if (qi == 2) { p0 *= y0; p1 *= y1; }
                    y0 = p0; y1 = p1;
                }
                __nv_bfloat162 h = __floats2bfloat162_rn(y0, y1);
                float2 f = __bfloat1622float2(h);
                __nv_bfloat162 l = __floats2bfloat162_rn(y0 - f.x, y1 - f.y);
                unsigned off = pos * 48 + icp * 4;
                *(unsigned*)(smem + CV_A_HI + off) = *(unsigned*)&h;
                *(unsigned*)(smem + CV_A_LO + off) = *(unsigned*)&l;
            }
        }
        // ---- stage weights: straight uint4 copy of pre-split planes ----
        {
            const uint4* Wh = Wh0 + cc * 1296;   // 10368 bf16 = 1296 uint4 per plane
            const uint4* Wl = Wl0 + cc * 1296;
            #pragma unroll
            for (int it = 0; it < 6; it++) {
                int i = tid + it * 256;
                if (i < 1296) {
                    ((uint4*)(smem + CV_W_HI))[i] = Wh[i];
                    ((uint4*)(smem + CV_W_LO))[i] = Wl[i];
                }
            }
        }
        __syncthreads();
        // ---- 9 taps: shifted A views + per-tap weights ----
        #pragma unroll
        for (int dy = 0; dy < 3; dy++)
            #pragma unroll
            for (int dx = 0; dx < 3; dx++) {
                unsigned ash = (unsigned)((dy * 68 + dx) * 48);
                unsigned ah[2][4], al[2][4];
                #pragma unroll
                for (int mt = 0; mt < 2; mt++) {
                    ldsm_x4(ah[mt], abase[mt] + ash);
                    ldsm_x4(al[mt], abase[mt] + ash + (CV_A_LO - CV_A_HI));
                }
                unsigned tw = sb + CV_W_HI + (dy * 3 + dx) * 2304 + bkrow * 144 + woc * 2;
                unsigned bh[4][2], bl[4][2];
                #pragma unroll
                for (int nt = 0; nt < 4; nt++) {
                    ldsm_x2t(bh[nt], tw + nt * 16);
                    ldsm_x2t(bl[nt], tw + nt * 16 + (CV_W_LO - CV_W_HI));
                }
                #pragma unroll
                for (int mt = 0; mt < 2; mt++)
                    #pragma unroll
                    for (int nt = 0; nt < 4; nt++) {
                        mma_bf16(acc[mt][nt], ah[mt], bh[nt]);
                        mma_bf16(acc[mt][nt], al[mt], bh[nt]);
                        mma_bf16(acc[mt][nt], ah[mt], bl[nt]);
                    }
            }
        __syncthreads();
    }

    // ---- epilogue: bias, store ----
    #pragma unroll
    for (int mt = 0; mt < 2; mt++)
        #pragma unroll
        for (int nt = 0; nt < 4; nt++) {
            int oc  = woc + nt * 8 + (lid & 3) * 2;
            int px0 = wpx + mt * 16 + (lid >> 2);
            int px1 = px0 + 8;
            float b0 = bias[oc], b1 = bias[oc + 1];
            float e0 = acc[mt][nt][0] + b0, e1 = acc[mt][nt][1] + b1;
            float e2 = acc[mt][nt][2] + b0, e3 = acc[mt][nt][3] + b1;
            if (FINAL) {
                int base = (b * CC + oc) << 12;
                int pxg0 = (h0 << 6) + px0;
                int pxg1 = (h0 << 6) + px1;
                out[base + pxg0]          = e0;
                out[base + 4096 + pxg0]   = e1;
                out[base + pxg1]          = e2;
                out[base + 4096 + pxg1]   = e3;
            } else {
                float* O = g_bottomT + b * (HW * CC);
                *(float2*)(O + ((h0 << 6) + px0) * CC + oc) = make_float2(e0, e1);
                *(float2*)(O + ((h0 << 6) + px1) * CC + oc) = make_float2(e2, e3);
            }
        }
}

// ---------------- K4: QK via mma.sync bf16-split + tile-local softmax ----------------
#define OFF_A_HI  128                       // [128 n][72 k] bf16 (144B rows)
#define OFF_A_LO  (OFF_A_HI + 128*144)
#define OFF_B_HI  (OFF_A_LO + 128*144)      // [64 k][136 m] bf16 (272B rows)
#define OFF_B_LO  (OFF_B_HI + 64*272)
#define SMEM_QK   (OFF_B_LO + 64*272)       // 71808 B

__global__ void __launch_bounds__(256, 2)
k_qk_mma() {
    extern __shared__ char smem[];
    unsigned sb;
    asm("{ .reg .u64 t; cvta.to.shared.u64 t, %1; cvt.u32.u64 %0, t; }"
        : "=r"(sb) : "l"(smem));
    int b  = blockIdx.z;
    int m0 = blockIdx.x * 128;
    int n0 = blockIdx.y * 128;
    int tid = threadIdx.x;
    int wid = tid >> 5, lid = tid & 31;
    float* s_red = (float*)smem;

    // ---- stage A (centerT rows, hi/lo) ----
    const float* Ag = g_centerT + (size_t)b * (HW * PP);
    #pragma unroll 2
    for (int it = 0; it < 8; it++) {
        int idx = tid + it * 256;          // 2048: n(128) x kf4(16)
        int n = idx >> 4, kf4 = idx & 15;
        float4 v = *(const float4*)(Ag + (n0 + n) * PP + 4 * kf4);
        unsigned hi[2], lo[2];
        cvt4(v, hi, lo);
        *(uint2*)(smem + OFF_A_HI + n * 144 + 8 * kf4) = make_uint2(hi[0], hi[1]);
        *(uint2*)(smem + OFF_A_LO + n * 144 + 8 * kf4) = make_uint2(lo[0], lo[1]);
    }
    // ---- stage B (top rows [k][m], hi/lo) ----
    const float* Bg = g_top + (size_t)b * (PP * HW) + m0;
    #pragma unroll 2
    for (int it = 0; it < 8; it++) {
        int idx = tid + it * 256;          // 2048: k(64) x mf4(32)
        int k = idx >> 5, mf4 = idx & 31;
        float4 v = *(const float4*)(Bg + k * HW + 4 * mf4);
        unsigned hi[2], lo[2];
        cvt4(v, hi, lo);
        *(uint2*)(smem + OFF_B_HI + k * 272 + 8 * mf4) = make_uint2(hi[0], hi[1]);
        *(uint2*)(smem + OFF_B_LO + k * 272 + 8 * mf4) = make_uint2(lo[0], lo[1]);
    }
    __syncthreads();

    int wn = (wid >> 1) * 32;
    int wm = (wid & 1) * 64;
    float acc[2][8][4];
    #pragma unroll
    for (int mt = 0; mt < 2; mt++)
        #pragma unroll
        for (int nt = 0; nt < 8; nt++)
            #pragma unroll
            for (int e = 0; e < 4; e++) acc[mt][nt][e] = 0.0f;

    int arow = wn + (lid & 15);
    int acolB = (lid >> 4) * 8;
    int bkrow = (lid & 15);

    #pragma unroll
    for (int ks = 0; ks < 4; ks++) {
        int k0 = ks * 16;
        unsigned ah[2][4], al[2][4];
        #pragma unroll
        for (int mt = 0; mt < 2; mt++) {
            unsigned aaddr = sb + OFF_A_HI + (arow + mt * 16) * 144 + (k0 + acolB) * 2;
            ldsm_x4(ah[mt], aaddr);
            ldsm_x4(al[mt], aaddr + (OFF_A_LO - OFF_A_HI));
        }
        unsigned bf[8][2];
        #pragma unroll
        for (int nt = 0; nt < 8; nt++)
            ldsm_x2t(bf[nt], sb + OFF_B_HI + (k0 + bkrow) * 272 + (wm + nt * 8) * 2);
        #pragma unroll
        for (int mt = 0; mt < 2; mt++)
            #pragma unroll
            for (int nt = 0; nt < 8; nt++) {
                mma_bf16(acc[mt][nt], ah[mt], bf[nt]);
                mma_bf16(acc[mt][nt], al[mt], bf[nt]);
            }
        #pragma unroll
        for (int nt = 0; nt < 8; nt++)
            ldsm_x2t(bf[nt], sb + OFF_B_LO + (k0 + bkrow) * 272 + (wm + nt * 8) * 2);
        #pragma unroll
        for (int mt = 0; mt < 2; mt++)
            #pragma unroll
            for (int nt = 0; nt < 8; nt++)
                mma_bf16(acc[mt][nt], ah[mt], bf[nt]);
    }

    // ---- tile max (block-wide) ----
    float mx = -INFINITY;
    #pragma unroll
    for (int mt = 0; mt < 2; mt++)
        #pragma unroll
        for (int nt = 0; nt < 8; nt++)
            #pragma unroll
            for (int e = 0; e < 4; e++)
                mx = fmaxf(mx, acc[mt][nt][e]);
    #pragma unroll
    for (int off = 16; off > 0; off >>= 1)
        mx = fmaxf(mx, __shfl_xor_sync(0xffffffffu, mx, off));
    if (lid == 0) s_red[wid] = mx;
    __syncthreads();
    float tmax = s_red[0];
    #pragma unroll
    for (int i = 1; i < 8; i++) tmax = fmaxf(tmax, s_red[i]);

    // ---- packed exp(sp - tmax) -> bf16, sum the ROUNDED values, store ----
    const u64 L2E   = dup2(1.4426950408889634f);
    const u64 TOFF  = dup2(-tmax * 1.4426950408889634f);
    const u64 MAGIC = dup2(12582912.0f);
    const u64 NMAG  = dup2(-12582912.0f);
    const u64 NEG1  = dup2(-1.0f);
    const u64 C6 = dup2(1.5403530e-4f), C5 = dup2(1.3333558e-3f);
    const u64 C4 = dup2(9.6181291e-3f), C3 = dup2(5.5504109e-2f);
    const u64 C2 = dup2(2.4022651e-1f), C1 = dup2(6.9314718e-1f);
    const u64 ONE = dup2(1.0f);
    float ssum = 0.0f;
    unsigned* Ho = g_sph + ((size_t)b << 23);
    int rbase = n0 + wn + (lid >> 2);
    int cbase = m0 + wm + (lid & 3) * 2;
    #pragma unroll
    for (int mt = 0; mt < 2; mt++)
        #pragma unroll
        for (int nt = 0; nt < 8; nt++) {
            u64 e01 = fexp2pair(pk2(acc[mt][nt][0], acc[mt][nt][1]),
                                L2E, TOFF, MAGIC, NMAG, NEG1,
                                C6, C5, C4, C3, C2, C1, ONE);
            u64 e23 = fexp2pair(pk2(acc[mt][nt][2], acc[mt][nt][3]),
                                L2E, TOFF, MAGIC, NMAG, NEG1,
                                C6, C5, C4, C3, C2, C1, ONE);
            float e0, e1, e2, e3;
            up2(e01, e0, e1); up2(e23, e2, e3);
            __nv_bfloat162 h01 = __floats2bfloat162_rn(e0, e1);
            __nv_bfloat162 h23 = __floats2bfloat162_rn(e2, e3);
            float2 f0 = __bfloat1622float2(h01);
            float2 f1 = __bfloat1622float2(h23);
            ssum += (f0.x + f0.y) + (f1.x + f1.y);
            int cc = cbase + nt * 8;
            Ho[((size_t)(rbase + mt * 16) * HW + cc) >> 1] = *(unsigned*)&h01;
            Ho[((size_t)(rbase + mt * 16 + 8) * HW + cc) >> 1] = *(unsigned*)&h23;
        }
    #pragma unroll
    for (int off = 16; off > 0; off >>= 1)
        ssum += __shfl_xor_sync(0xffffffffu, ssum, off);
    __syncthreads();
    if (lid == 0) s_red[wid] = ssum;
    __syncthreads();
    if (tid == 0) {
        float t = 0.0f;
        #pragma unroll
        for (int i = 0; i < 8; i++) t += s_red[i];
        int tile = blockIdx.y * 32 + blockIdx.x;
        g_tmax[b][tile] = tmax;
        g_tsum[b][tile] = t;
    }
}

// ---------------- K5: combine per-tile (max,sum) -> global (max,sum) ----------------
__global__ void k_combine() {
    int b = blockIdx.x;
    int tid = threadIdx.x;               // 1024 threads, one per tile
    __shared__ float s_red[32];
    float v = g_tmax[b][tid];
    float mx = v;
    #pragma unroll
    for (int off = 16; off > 0; off >>= 1)
        mx = fmaxf(mx, __shfl_xor_sync(0xffffffffu, mx, off));
    if ((tid & 31) == 0) s_red[tid >> 5] = mx;
    __syncthreads();
    if (tid < 32) {
        float m2 = s_red[tid];
        #pragma unroll
        for (int off = 16; off > 0; off >>= 1)
            m2 = fmaxf(m2, __shfl_xor_sync(0xffffffffu, m2, off));
        if (tid == 0) s_red[0] = m2;
    }
    __syncthreads();
    float gmax = s_red[0];
    __syncthreads();
    float part = g_tsum[b][tid] * fexp(v - gmax);
    #pragma unroll
    for (int off = 16; off > 0; off >>= 1)
        part += __shfl_xor_sync(0xffffffffu, part, off);
    __shared__ float s_sum[32];
    if ((tid & 31) == 0) s_sum[tid >> 5] = part;
    __syncthreads();
    if (tid < 32) {
        float t = s_sum[tid];
        #pragma unroll
        for (int off = 16; off > 0; off >>= 1)
            t += __shfl_xor_sync(0xffffffffu, t, off);
        if (tid == 0) { g_max[b] = gmax; g_sum[b] = t; }
    }
}

// ---------------- K6: spv = E @ bottomT via mma.sync (E bf16, B split), split-K 2 ----
#define AV_A_HI 0                           // [128 n][72 k] bf16 (144B rows)
#define AV_B_HI (AV_A_HI + 128*144)         // [64 k][72 c] bf16 (144B rows)
#define AV_B_LO (AV_B_HI + 64*144)
#define SMEM_AV (AV_B_LO + 64*144)          // 36864 B

__global__ void __launch_bounds__(256, 3)
k_av_mma() {
    extern __shared__ char smem[];
    unsigned sb;
    asm("{ .reg .u64 t; cvta.to.shared.u64 t, %1; cvt.u32.u64 %0, t; }"
        : "=r"(sb) : "l"(smem));
    int b  = blockIdx.z;
    int ks = blockIdx.y;
    int n0 = blockIdx.x * 128;
    int tid = threadIdx.x;
    int wid = tid >> 5, lid = tid & 31;
    int wn = (wid >> 1) * 32;       // warp rows
    int wc = (wid & 1) * 32;        // warp cols
    const unsigned* Hp = g_sph + ((size_t)b << 23);
    const float* BT = g_bottomT + b * (HW * CC);
    float gmax = g_max[b];
    int trow = (n0 >> 7) * 32;

    float acc[2][4][4];
    #pragma unroll
    for (int mt = 0; mt < 2; mt++)
        #pragma unroll
        for (int nt = 0; nt < 4; nt++)
            #pragma unroll
            for (int e = 0; e < 4; e++) acc[mt][nt][e] = 0.0f;

    int arow = wn + (lid & 15);
    int acolB = (lid >> 4) * 8;
    int bkrow = (lid & 15);

    for (int kc = 0; kc < 2048; kc += 64) {
        int kbase = ks * 2048 + kc;
        // ---- stage A: bf16 E plane straight from gmem ----
        #pragma unroll
        for (int it = 0; it < 4; it++) {
            int idx = tid + it * 256;              // 1024: row(128) x j(8)
            int row = idx >> 3, j = idx & 7;
            size_t off = (size_t)(n0 + row) * (HW / 2) + (kbase >> 1) + j * 4;
            *(uint4*)(smem + AV_A_HI + row * 144 + j * 16) = *(const uint4*)(Hp + off);
        }
        // ---- stage B: bottomT scaled by s(k-strip), bf16-split in regs ----
        float s = fexp(g_tmax[b][trow + (kbase >> 7)] - gmax);
        #pragma unroll
        for (int it = 0; it < 4; it++) {
            int idx = tid + it * 256;              // 1024: k(64) x j(16)
            int k = idx >> 4, j = idx & 15;
            float4 v = *(const float4*)(BT + (kbase + k) * CC + 4 * j);
            v.x *= s; v.y *= s; v.z *= s; v.w *= s;
            unsigned hi[2], lo[2];
            cvt4(v, hi, lo);
            *(uint2*)(smem + AV_B_HI + k * 144 + j * 8) = make_uint2(hi[0], hi[1]);
            *(uint2*)(smem + AV_B_LO + k * 144 + j * 8) = make_uint2(lo[0], lo[1]);
        }
        __syncthreads();
        // ---- 4 k-steps of 16 ----
        #pragma unroll
        for (int k8 = 0; k8 < 4; k8++) {
            int k0 = k8 * 16;
            unsigned ah[2][4];
            #pragma unroll
            for (int mt = 0; mt < 2; mt++)
                ldsm_x4(ah[mt], sb + AV_A_HI + (arow + mt * 16) * 144 + (k0 + acolB) * 2);
            unsigned bh[4][2], bl[4][2];
            #pragma unroll
            for (int nt = 0; nt < 4; nt++) {
                unsigned baddr = sb + AV_B_HI + (k0 + bkrow) * 144 + (wc + nt * 8) * 2;
                ldsm_x2t(bh[nt], baddr);
                ldsm_x2t(bl[nt], baddr + (AV_B_LO - AV_B_HI));
            }
            #pragma unroll
            for (int mt = 0; mt < 2; mt++)
                #pragma unroll
                for (int nt = 0; nt < 4; nt++) {
                    mma_bf16(acc[mt][nt], ah[mt], bh[nt]);
                    mma_bf16(acc[mt][nt], ah[mt], bl[nt]);
                }
        }
        __syncthreads();
    }

    // ---- epilogue: / gsum, write split-K partial ----
    float inv = 1.0f / g_sum[b];
    float* O = g_spv[ks] + b * (HW * CC);
    int rbase = n0 + wn + (lid >> 2);
    int cbase = wc + (lid & 3) * 2;
    #pragma unroll
    for (int mt = 0; mt < 2; mt++)
        #pragma unroll
        for (int nt = 0; nt < 4; nt++) {
            int cc = cbase + nt * 8;
            *(float2*)(O + (rbase + mt * 16) * CC + cc) =
                make_float2(acc[mt][nt][0] * inv, acc[mt][nt][1] * inv);
            *(float2*)(O + (rbase + mt * 16 + 8) * CC + cc) =
                make_float2(acc[mt][nt][2] * inv, acc[mt][nt][3] * inv);
        }
}

// ---------------- launch ----------------
extern "C" void kernel_launch(void* const* d_in, const int* in_sizes, int n_in,
                              void* d_out, int out_size) {
    (void)in_sizes; (void)n_in; (void)out_size;
    const float* x     = (const float*)d_in[0];
    const float* top_w = (const float*)d_in[1];
    const float* top_b = (const float*)d_in[2];
    const float* cen_w = (const float*)d_in[3];
    const float* cen_b = (const float*)d_in[4];
    const float* bot_w = (const float*)d_in[5];
    const float* bot_b = (const float*)d_in[6];
    const float* out_w = (const float*)d_in[7];
    const float* out_b = (const float*)d_in[8];
    float* out = (float*)d_out;

    cudaFuncSetAttribute(k_qk_mma, cudaFuncAttributeMaxDynamicSharedMemorySize, SMEM_QK);
    cudaFuncSetAttribute(k_av_mma, cudaFuncAttributeMaxDynamicSharedMemorySize, SMEM_AV);
    cudaFuncSetAttribute(k_conv3<false>, cudaFuncAttributeMaxDynamicSharedMemorySize, SMEM_CV);
    cudaFuncSetAttribute(k_conv3<true>,  cudaFuncAttributeMaxDynamicSharedMemorySize, SMEM_CV);

    k_wprep<<<(WCV_N + 255) / 256, 256>>>(bot_w, out_w);
    k_proj<<<dim3(64, 4), 256>>>(x, top_w, top_b, cen_w, cen_b);
    k_conv3<false><<<dim3(32, 4), 256, SMEM_CV>>>(bot_b, x, nullptr);
    k_qk_mma<<<dim3(32, 32, 4), 256, SMEM_QK>>>();
    k_combine<<<4, 1024>>>();
    k_av_mma<<<dim3(32, 2, 4), 256, SMEM_AV>>>();
    k_conv3<true><<<dim3(32, 4), 256, SMEM_CV>>>(out_b, x, out);
}